// round 1
// baseline (speedup 1.0000x reference)
#include <cuda_runtime.h>
#include <math.h>

// ---------------- constants ----------------
constexpr int Bc = 8, Tc = 2048, Ec = 256, Hc = 2, HDc = 128, M2c = 134;
constexpr int BT = Bc * Tc;            // 16384 rows
constexpr int QT = 64, KT = 32;        // attention tile sizes

// ---------------- scratch (device globals; no allocations allowed) --------
__device__ float g_x[BT * Ec];         // residual stream
__device__ float g_h[BT * Ec];         // LN outputs
__device__ float g_qkv[BT * 3 * Ec];   // qkv
__device__ float g_y[BT * Ec];         // attention output
__device__ float g_fc[BT * 2 * Ec];    // fc hidden
__device__ float g_part[64 * Ec];      // mean-pool partials (8 chunks x 8 batch x 256)

// ---------------- embed: x = relu(X + wpe[t] + wpe[cls(t)]) ----------------
__global__ void embed_kernel(const float* __restrict__ X,
                             const float* __restrict__ wpe,
                             float* __restrict__ out) {
    int i4 = blockIdx.x * 256 + threadIdx.x;        // over BT*E/4
    int e4 = i4 & (Ec / 4 - 1);                     // Ec/4 = 64
    int t  = (i4 >> 6) & (Tc - 1);
    float4 x  = ((const float4*)X)[i4];
    float4 w  = ((const float4*)wpe)[t * (Ec / 4) + e4];
    float4 w2 = ((const float4*)wpe)[(t >= Tc / 2 ? 1 : 0) * (Ec / 4) + e4];
    float4 o;
    o.x = fmaxf(x.x + w.x + w2.x, 0.f);
    o.y = fmaxf(x.y + w.y + w2.y, 0.f);
    o.z = fmaxf(x.z + w.z + w2.z, 0.f);
    o.w = fmaxf(x.w + w.w + w2.w, 0.f);
    ((float4*)out)[i4] = o;
}

// ---------------- layernorm over E=256 (one block per row) ----------------
__global__ void ln_kernel(const float* __restrict__ in,
                          const float* __restrict__ g,
                          const float* __restrict__ b,
                          float* __restrict__ out, int relu_out) {
    int row = blockIdx.x;
    int tid = threadIdx.x;
    __shared__ float rb[8];
    float v = in[row * Ec + tid];
    float s = v;
    #pragma unroll
    for (int o = 16; o; o >>= 1) s += __shfl_xor_sync(~0u, s, o);
    if ((tid & 31) == 0) rb[tid >> 5] = s;
    __syncthreads();
    float tot = 0;
    #pragma unroll
    for (int i = 0; i < 8; i++) tot += rb[i];
    float mu = tot * (1.f / Ec);
    float d = v - mu;
    float s2 = d * d;
    #pragma unroll
    for (int o = 16; o; o >>= 1) s2 += __shfl_xor_sync(~0u, s2, o);
    __syncthreads();
    if ((tid & 31) == 0) rb[tid >> 5] = s2;
    __syncthreads();
    float tot2 = 0;
    #pragma unroll
    for (int i = 0; i < 8; i++) tot2 += rb[i];
    float r = rsqrtf(tot2 * (1.f / Ec) + 1e-5f);
    float o = d * r * g[tid] + b[tid];
    if (relu_out) o = fmaxf(o, 0.f);
    out[row * Ec + tid] = o;
}

// ---------------- GEMM: C[M,N] = act( A[M,K] @ W[N,K]^T + bias (+res) ) ----
// 64x64 block tile, BK=16, 256 threads, 4x4 micro-tile per thread.
__global__ void __launch_bounds__(256)
gemm_kernel(const float* __restrict__ A, const float* __restrict__ W,
            const float* __restrict__ bias, const float* __restrict__ res,
            float* __restrict__ C, int M, int N, int K, int relu, int addres) {
    __shared__ float As[16][64];
    __shared__ float Bs[16][64];
    int tid = threadIdx.x;
    int bm = blockIdx.y * 64, bn = blockIdx.x * 64;
    int tx = tid & 15, ty = tid >> 4;
    int lr = tid >> 2, ls = tid & 3;
    float acc[16];
    #pragma unroll
    for (int i = 0; i < 16; i++) acc[i] = 0.f;

    for (int k0 = 0; k0 < K; k0 += 16) {
        float4 a4 = *(const float4*)(A + (bm + lr) * K + k0 + ls * 4);
        float4 b4 = *(const float4*)(W + (bn + lr) * K + k0 + ls * 4);
        As[ls * 4 + 0][lr] = a4.x; As[ls * 4 + 1][lr] = a4.y;
        As[ls * 4 + 2][lr] = a4.z; As[ls * 4 + 3][lr] = a4.w;
        Bs[ls * 4 + 0][lr] = b4.x; Bs[ls * 4 + 1][lr] = b4.y;
        Bs[ls * 4 + 2][lr] = b4.z; Bs[ls * 4 + 3][lr] = b4.w;
        __syncthreads();
        #pragma unroll
        for (int kk = 0; kk < 16; kk++) {
            float4 am = *(const float4*)&As[kk][ty * 4];
            float4 bv = *(const float4*)&Bs[kk][tx * 4];
            float a_[4] = {am.x, am.y, am.z, am.w};
            float b_[4] = {bv.x, bv.y, bv.z, bv.w};
            #pragma unroll
            for (int i = 0; i < 4; i++)
                #pragma unroll
                for (int j = 0; j < 4; j++)
                    acc[i * 4 + j] += a_[i] * b_[j];
        }
        __syncthreads();
    }
    #pragma unroll
    for (int i = 0; i < 4; i++) {
        int m = bm + ty * 4 + i;
        #pragma unroll
        for (int j = 0; j < 4; j++) {
            int n = bn + tx * 4 + j;
            float v = acc[i * 4 + j] + bias[n];
            if (addres) v += res[m * N + n];
            if (relu) v = fmaxf(v, 0.f);
            C[m * N + n] = v;
        }
    }
}

// ---------------- attention: y = (relu(qk^T/sqrt(d)) * causal) @ v ---------
// One block per (q-tile of 64 rows, b*h). Streams 32-row K/V tiles.
constexpr int ATTN_SMEM_FLOATS = QT * HDc + KT * (HDc + 1) + KT * HDc + QT * (KT + 1);
constexpr int ATTN_SMEM = ATTN_SMEM_FLOATS * 4;   // 74112 bytes

__global__ void __launch_bounds__(256)
attn_kernel(const float* __restrict__ qkv, float* __restrict__ y) {
    extern __shared__ float sm[];
    float* Qs = sm;                         // [QT][HDc]
    float* Ks = Qs + QT * HDc;              // [KT][HDc+1]  (pad kills bank conflicts)
    float* Vs = Ks + KT * (HDc + 1);        // [KT][HDc]
    float* Ss = Vs + KT * HDc;              // [QT][KT+1]

    int qt = blockIdx.x;
    int bh = blockIdx.y;
    int b = bh / Hc, h = bh % Hc;
    int tid = threadIdx.x;
    int ty = tid >> 5, tx = tid & 31;
    const float scale = 0.08838834764831845f;   // 1/sqrt(128)
    int baserow = b * Tc;

    // load Q tile
    for (int i = tid; i < QT * HDc / 4; i += 256) {
        int r = i / (HDc / 4), d4 = i % (HDc / 4);
        float4 q = *(const float4*)(qkv + (baserow + qt * QT + r) * 768 + h * HDc + d4 * 4);
        *(float4*)(Qs + r * HDc + d4 * 4) = q;
    }

    float acc[32];
    #pragma unroll
    for (int i = 0; i < 32; i++) acc[i] = 0.f;

    int nkt = 2 * qt + 2;   // causal: k tiles up to q_hi = qt*64+63
    for (int kt = 0; kt < nkt; kt++) {
        __syncthreads();   // protect prev-iter Ss/Vs reads (+ first-iter Q visibility)
        for (int i = tid; i < KT * HDc / 4; i += 256) {
            int r = i / (HDc / 4), d4 = i % (HDc / 4);
            const float* base = qkv + (baserow + kt * KT + r) * 768 + h * HDc + d4 * 4;
            float4 k4 = *(const float4*)(base + 256);
            Ks[r * (HDc + 1) + d4 * 4 + 0] = k4.x;
            Ks[r * (HDc + 1) + d4 * 4 + 1] = k4.y;
            Ks[r * (HDc + 1) + d4 * 4 + 2] = k4.z;
            Ks[r * (HDc + 1) + d4 * 4 + 3] = k4.w;
            float4 v4 = *(const float4*)(base + 512);
            *(float4*)(Vs + r * HDc + d4 * 4) = v4;
        }
        __syncthreads();

        // S phase: thread (ty,tx) computes S[ty*8+j][tx] for j=0..7
        float s[8];
        #pragma unroll
        for (int j = 0; j < 8; j++) s[j] = 0.f;
        const float* kr = Ks + tx * (HDc + 1);
        const float* qr = Qs + (ty * 8) * HDc;
        #pragma unroll 4
        for (int d = 0; d < HDc; d++) {
            float kv = kr[d];
            #pragma unroll
            for (int j = 0; j < 8; j++) s[j] += qr[j * HDc + d] * kv;
        }
        int kg = kt * KT + tx;
        #pragma unroll
        for (int j = 0; j < 8; j++) {
            int qg = qt * QT + ty * 8 + j;
            float v = s[j] * scale;
            v = (kg <= qg) ? fmaxf(v, 0.f) : 0.f;
            Ss[(ty * 8 + j) * (KT + 1) + tx] = v;
        }
        __syncthreads();

        // accumulate phase: thread owns y rows ty*8..ty*8+7, cols tx*4..tx*4+3
        for (int kk = 0; kk < KT; kk++) {
            float4 v4 = *(const float4*)(Vs + kk * HDc + tx * 4);
            #pragma unroll
            for (int jr = 0; jr < 8; jr++) {
                float sv = Ss[(ty * 8 + jr) * (KT + 1) + kk];
                acc[jr * 4 + 0] += sv * v4.x;
                acc[jr * 4 + 1] += sv * v4.y;
                acc[jr * 4 + 2] += sv * v4.z;
                acc[jr * 4 + 3] += sv * v4.w;
            }
        }
    }
    #pragma unroll
    for (int jr = 0; jr < 8; jr++) {
        int t = qt * QT + ty * 8 + jr;
        float4 o = make_float4(acc[jr * 4], acc[jr * 4 + 1], acc[jr * 4 + 2], acc[jr * 4 + 3]);
        *(float4*)(y + (baserow + t) * Ec + h * HDc + tx * 4) = o;
    }
}

// ---------------- mean over T: partial sums (deterministic, no atomics) ----
__global__ void meanpart_kernel(const float* __restrict__ xf, float* __restrict__ part) {
    int c = blockIdx.x;      // t-chunk 0..7
    int b = blockIdx.y;      // batch
    int e = threadIdx.x;
    float s = 0.f;
    for (int tt = 0; tt < 256; tt++) {
        int t = c * 256 + tt;
        s += xf[(b * Tc + t) * Ec + e];
    }
    part[(c * Bc + b) * Ec + e] = s;
}

// ---------------- final: emb, logits, losses, outputs ----------------------
__global__ void final_kernel(const float* __restrict__ part,
                             const float* __restrict__ head_w,
                             const float* __restrict__ head_b,
                             const float* __restrict__ Y,
                             float* __restrict__ out) {
    __shared__ float emb[Bc * Ec];     // 2048
    __shared__ float lg[Bc * M2c];     // 1072
    __shared__ float rb[8];
    int tid = threadIdx.x;

    for (int i = tid; i < Bc * Ec; i += 256) {
        int b = i >> 8, e = i & 255;
        float s = 0.f;
        #pragma unroll
        for (int c = 0; c < 8; c++) s += part[(c * Bc + b) * Ec + e];
        emb[i] = s * (1.f / Tc);
    }
    __syncthreads();

    // logits + loss1 accumulation
    float l1 = 0.f;
    for (int o = tid; o < Bc * M2c; o += 256) {
        int b = o / M2c, m = o % M2c;
        float s = head_b[m];
        const float* wr = head_w + m * Ec;
        const float* er = emb + b * Ec;
        #pragma unroll 4
        for (int k = 0; k < Ec; k++) s += er[k] * wr[k];
        s = fmaxf(s, 0.f);
        lg[o] = s;
        float d = s - Y[o];
        l1 += d * d;
    }
    #pragma unroll
    for (int o = 16; o; o >>= 1) l1 += __shfl_xor_sync(~0u, l1, o);
    __syncthreads();
    if ((tid & 31) == 0) rb[tid >> 5] = l1;
    __syncthreads();
    float tot1 = 0.f;
    #pragma unroll
    for (int i = 0; i < 8; i++) tot1 += rb[i];
    float loss1 = sqrtf(tot1 / (float)(Bc * M2c));

    // e1/e2 write + loss3
    float l3 = 0.f;
    for (int i = tid; i < Bc * (Ec / 2); i += 256) {
        int b = i / (Ec / 2), j = i % (Ec / 2);
        float e1 = emb[b * Ec + j];
        float e2 = emb[b * Ec + Ec / 2 + j];
        out[i] = e1;
        out[Bc * (Ec / 2) + i] = e2;
        float d = e1 - e2;
        l3 += d * d;
    }
    #pragma unroll
    for (int o = 16; o; o >>= 1) l3 += __shfl_xor_sync(~0u, l3, o);
    __syncthreads();
    if ((tid & 31) == 0) rb[tid >> 5] = l3;
    __syncthreads();
    float tot3 = 0.f;
    #pragma unroll
    for (int i = 0; i < 8; i++) tot3 += rb[i];
    float loss3 = sqrtf(tot3 / (float)(Bc * Ec / 2));

    int off = 2 * Bc * (Ec / 2);   // 2048
    if (tid == 0) {
        out[off + 0] = 50.f * loss1 + loss3;
        out[off + 1] = loss1;
        out[off + 2] = loss3;
    }
    for (int o = tid; o < Bc * M2c; o += 256) out[off + 3 + o] = lg[o];
}

// ---------------- host launcher --------------------------------------------
extern "C" void kernel_launch(void* const* d_in, const int* in_sizes, int n_in,
                              void* d_out, int out_size) {
    const float* X          = (const float*)d_in[0];
    const float* Y          = (const float*)d_in[1];
    const float* wpe        = (const float*)d_in[2];
    const float* ln1_g      = (const float*)d_in[3];
    const float* ln1_b      = (const float*)d_in[4];
    const float* attn_w     = (const float*)d_in[5];
    const float* attn_b     = (const float*)d_in[6];
    const float* attnproj_w = (const float*)d_in[7];
    const float* attnproj_b = (const float*)d_in[8];
    const float* ln2_g      = (const float*)d_in[9];
    const float* ln2_b      = (const float*)d_in[10];
    const float* fc_w       = (const float*)d_in[11];
    const float* fc_b       = (const float*)d_in[12];
    const float* mlpproj_w  = (const float*)d_in[13];
    const float* mlpproj_b  = (const float*)d_in[14];
    const float* lnf_g      = (const float*)d_in[15];
    const float* lnf_b      = (const float*)d_in[16];
    const float* head_w     = (const float*)d_in[17];
    const float* head_b     = (const float*)d_in[18];

    float *x, *h, *qkv, *y, *fc, *part;
    cudaGetSymbolAddress((void**)&x, g_x);
    cudaGetSymbolAddress((void**)&h, g_h);
    cudaGetSymbolAddress((void**)&qkv, g_qkv);
    cudaGetSymbolAddress((void**)&y, g_y);
    cudaGetSymbolAddress((void**)&fc, g_fc);
    cudaGetSymbolAddress((void**)&part, g_part);

    cudaFuncSetAttribute(attn_kernel, cudaFuncAttributeMaxDynamicSharedMemorySize, ATTN_SMEM);

    // x = relu(X + wpe + wpe[cls])
    embed_kernel<<<BT * Ec / 4 / 256, 256>>>(X, wpe, x);
    // h = ln1(x)
    ln_kernel<<<BT, 256>>>(x, ln1_g, ln1_b, h, 0);
    // qkv = relu(h @ attn_w^T + attn_b)
    gemm_kernel<<<dim3(768 / 64, BT / 64), 256>>>(h, attn_w, attn_b, nullptr, qkv, BT, 768, 256, 1, 0);
    // y = causal relu-attention
    attn_kernel<<<dim3(Tc / QT, Bc * Hc), 256, ATTN_SMEM>>>(qkv, y);
    // x = x + y @ attnproj_w^T + attnproj_b
    gemm_kernel<<<dim3(256 / 64, BT / 64), 256>>>(y, attnproj_w, attnproj_b, x, x, BT, 256, 256, 0, 1);
    // h = ln2(x)
    ln_kernel<<<BT, 256>>>(x, ln2_g, ln2_b, h, 0);
    // fc = relu(h @ fc_w^T + fc_b)
    gemm_kernel<<<dim3(512 / 64, BT / 64), 256>>>(h, fc_w, fc_b, nullptr, fc, BT, 512, 256, 1, 0);
    // x = relu(x + fc @ mlpproj_w^T + mlpproj_b)
    gemm_kernel<<<dim3(256 / 64, BT / 64), 256>>>(fc, mlpproj_w, mlpproj_b, x, x, BT, 256, 512, 1, 1);
    // h = relu(lnf(x))
    ln_kernel<<<BT, 256>>>(x, lnf_g, lnf_b, h, 1);
    // mean over T (two-pass, deterministic)
    meanpart_kernel<<<dim3(8, Bc), 256>>>(h, part);
    // emb, logits, losses, outputs
    final_kernel<<<1, 256>>>(part, head_w, head_b, Y, (float*)d_out);
}

// round 3
// speedup vs baseline: 1.1376x; 1.1376x over previous
#include <cuda_runtime.h>
#include <math.h>

// ---------------- constants ----------------
constexpr int Bc = 8, Tc = 2048, Ec = 256, Hc = 2, HDc = 128, M2c = 134;
constexpr int BT = Bc * Tc;            // 16384 rows
constexpr int QT = 64, KT = 64;        // attention tile sizes

typedef unsigned long long u64;

// packed f32x2 helpers (SASS FFMA2 — 2 fp32 FMAs per issue slot)
__device__ __forceinline__ u64 fma2(u64 a, u64 b, u64 c) {
    u64 d; asm("fma.rn.f32x2 %0, %1, %2, %3;" : "=l"(d) : "l"(a), "l"(b), "l"(c)); return d;
}
__device__ __forceinline__ u64 dup2(float x) {
    u64 d; asm("mov.b64 %0, {%1, %1};" : "=l"(d) : "f"(x)); return d;
}
__device__ __forceinline__ void unpack2(u64 v, float& lo, float& hi) {
    asm("mov.b64 {%0, %1}, %2;" : "=f"(lo), "=f"(hi) : "l"(v));
}

// ---------------- scratch (device globals; no allocations allowed) --------
__device__ float g_x[BT * Ec];         // residual stream
__device__ float g_h[BT * Ec];         // LN outputs
__device__ float g_qkv[BT * 3 * Ec];   // qkv
__device__ float g_y[BT * Ec];         // attention output
__device__ float g_fc[BT * 2 * Ec];    // fc hidden
__device__ float g_part[64 * Ec];      // mean-pool partials

// ---------------- embed: x = relu(X + wpe[t] + wpe[cls(t)]) ----------------
__global__ void embed_kernel(const float* __restrict__ X,
                             const float* __restrict__ wpe,
                             float* __restrict__ out) {
    int i4 = blockIdx.x * 256 + threadIdx.x;
    int e4 = i4 & (Ec / 4 - 1);
    int t  = (i4 >> 6) & (Tc - 1);
    float4 x  = ((const float4*)X)[i4];
    float4 w  = ((const float4*)wpe)[t * (Ec / 4) + e4];
    float4 w2 = ((const float4*)wpe)[(t >= Tc / 2 ? 1 : 0) * (Ec / 4) + e4];
    float4 o;
    o.x = fmaxf(x.x + w.x + w2.x, 0.f);
    o.y = fmaxf(x.y + w.y + w2.y, 0.f);
    o.z = fmaxf(x.z + w.z + w2.z, 0.f);
    o.w = fmaxf(x.w + w.w + w2.w, 0.f);
    ((float4*)out)[i4] = o;
}

// ---------------- layernorm over E=256 (one block per row) ----------------
__global__ void ln_kernel(const float* __restrict__ in,
                          const float* __restrict__ g,
                          const float* __restrict__ b,
                          float* __restrict__ out, int relu_out) {
    int row = blockIdx.x;
    int tid = threadIdx.x;
    __shared__ float rb[8];
    float v = in[row * Ec + tid];
    float s = v;
    #pragma unroll
    for (int o = 16; o; o >>= 1) s += __shfl_xor_sync(~0u, s, o);
    if ((tid & 31) == 0) rb[tid >> 5] = s;
    __syncthreads();
    float tot = 0;
    #pragma unroll
    for (int i = 0; i < 8; i++) tot += rb[i];
    float mu = tot * (1.f / Ec);
    float d = v - mu;
    float s2 = d * d;
    #pragma unroll
    for (int o = 16; o; o >>= 1) s2 += __shfl_xor_sync(~0u, s2, o);
    __syncthreads();
    if ((tid & 31) == 0) rb[tid >> 5] = s2;
    __syncthreads();
    float tot2 = 0;
    #pragma unroll
    for (int i = 0; i < 8; i++) tot2 += rb[i];
    float r = rsqrtf(tot2 * (1.f / Ec) + 1e-5f);
    float o = d * r * g[tid] + b[tid];
    if (relu_out) o = fmaxf(o, 0.f);
    out[row * Ec + tid] = o;
}

// ---------------- GEMM: C[M,N] = act( A[M,K] @ W[N,K]^T + bias (+res) ) ----
// 128x128 tile, BK=16, 256 threads, 8x8 micro-tile, f32x2 packed FMAs,
// register-prefetch single-buffer pipeline.
constexpr int BM = 128, BN = 128, BKg = 16;

__global__ void __launch_bounds__(256)
gemm_kernel(const float* __restrict__ A, const float* __restrict__ W,
            const float* __restrict__ bias, const float* __restrict__ res,
            float* __restrict__ C, int M, int N, int K, int relu, int addres) {
    __shared__ float As[BKg][BM];   // [k][m]
    __shared__ float Bs[BKg][BN];   // [k][n]
    int tid = threadIdx.x;
    int bm = blockIdx.y * BM, bn = blockIdx.x * BN;
    int tx = tid & 15, ty = tid >> 4;

    int lm0 = tid >> 2, lkg = tid & 3;
    int lm1 = lm0 + 64;

    u64 acc[8][4];
    #pragma unroll
    for (int i = 0; i < 8; i++)
        #pragma unroll
        for (int j = 0; j < 4; j++) acc[i][j] = 0ull;

    float4 pa0 = *(const float4*)(A + (bm + lm0) * K + lkg * 4);
    float4 pa1 = *(const float4*)(A + (bm + lm1) * K + lkg * 4);
    float4 pb0 = *(const float4*)(W + (bn + lm0) * K + lkg * 4);
    float4 pb1 = *(const float4*)(W + (bn + lm1) * K + lkg * 4);

    for (int k0 = 0; k0 < K; k0 += BKg) {
        __syncthreads();
        As[lkg * 4 + 0][lm0] = pa0.x; As[lkg * 4 + 1][lm0] = pa0.y;
        As[lkg * 4 + 2][lm0] = pa0.z; As[lkg * 4 + 3][lm0] = pa0.w;
        As[lkg * 4 + 0][lm1] = pa1.x; As[lkg * 4 + 1][lm1] = pa1.y;
        As[lkg * 4 + 2][lm1] = pa1.z; As[lkg * 4 + 3][lm1] = pa1.w;
        Bs[lkg * 4 + 0][lm0] = pb0.x; Bs[lkg * 4 + 1][lm0] = pb0.y;
        Bs[lkg * 4 + 2][lm0] = pb0.z; Bs[lkg * 4 + 3][lm0] = pb0.w;
        Bs[lkg * 4 + 0][lm1] = pb1.x; Bs[lkg * 4 + 1][lm1] = pb1.y;
        Bs[lkg * 4 + 2][lm1] = pb1.z; Bs[lkg * 4 + 3][lm1] = pb1.w;
        __syncthreads();

        if (k0 + BKg < K) {
            int kn = k0 + BKg;
            pa0 = *(const float4*)(A + (bm + lm0) * K + kn + lkg * 4);
            pa1 = *(const float4*)(A + (bm + lm1) * K + kn + lkg * 4);
            pb0 = *(const float4*)(W + (bn + lm0) * K + kn + lkg * 4);
            pb1 = *(const float4*)(W + (bn + lm1) * K + kn + lkg * 4);
        }

        #pragma unroll
        for (int kk = 0; kk < BKg; kk++) {
            float4 av0 = *(const float4*)&As[kk][ty * 4];
            float4 av1 = *(const float4*)&As[kk][ty * 4 + 64];
            ulonglong2 bv0 = *(const ulonglong2*)&Bs[kk][tx * 4];
            ulonglong2 bv1 = *(const ulonglong2*)&Bs[kk][tx * 4 + 64];
            u64 b2[4] = {bv0.x, bv0.y, bv1.x, bv1.y};
            float aa[8] = {av0.x, av0.y, av0.z, av0.w, av1.x, av1.y, av1.z, av1.w};
            #pragma unroll
            for (int i = 0; i < 8; i++) {
                u64 ad = dup2(aa[i]);
                #pragma unroll
                for (int j = 0; j < 4; j++) acc[i][j] = fma2(ad, b2[j], acc[i][j]);
            }
        }
    }

    #pragma unroll
    for (int i = 0; i < 8; i++) {
        int m = bm + (i < 4 ? ty * 4 + i : 64 + ty * 4 + i - 4);
        #pragma unroll
        for (int half = 0; half < 2; half++) {
            int n0 = bn + half * 64 + tx * 4;
            float v0, v1, v2, v3;
            unpack2(acc[i][half * 2 + 0], v0, v1);
            unpack2(acc[i][half * 2 + 1], v2, v3);
            v0 += bias[n0 + 0]; v1 += bias[n0 + 1];
            v2 += bias[n0 + 2]; v3 += bias[n0 + 3];
            if (addres) {
                const float* rr = res + m * N + n0;
                v0 += rr[0]; v1 += rr[1]; v2 += rr[2]; v3 += rr[3];
            }
            if (relu) {
                v0 = fmaxf(v0, 0.f); v1 = fmaxf(v1, 0.f);
                v2 = fmaxf(v2, 0.f); v3 = fmaxf(v3, 0.f);
            }
            *(float4*)(C + m * N + n0) = make_float4(v0, v1, v2, v3);
        }
    }
}

// ---------------- attention: y = (relu(qk^T/sqrt(d)) * causal) @ v ---------
// 64x64 tiles, transposed Q/K smem, f32x2 math.
// S phase: (ty,tx) 16x16 grid, 4x4 micro-tile over (q,k).
// AV phase: (ty,tx) — q rows ty*4..+3, d cols tx*8..+7 (16*8 = 128 = HD). 
constexpr int ATTN_SMEM = (HDc * QT + HDc * KT + KT * HDc + QT * 68) * 4;  // 115712 B

__global__ void __launch_bounds__(256)
attn_kernel(const float* __restrict__ qkv, float* __restrict__ y) {
    extern __shared__ float sm[];
    float* QsT = sm;                    // [d][q]   128x64
    float* KsT = QsT + HDc * QT;        // [d][k]   128x64
    float* Vs  = KsT + HDc * KT;        // [k][d]   64x128
    float* Ss  = Vs + KT * HDc;         // [q][k]   64x68 (padded)

    int qt = gridDim.x - 1 - blockIdx.x;    // heavy causal blocks first
    int bh = blockIdx.y;
    int b = bh >> 1, h = bh & 1;
    int tid = threadIdx.x;
    int tx = tid & 15, ty = tid >> 4;
    const float scale = 0.08838834764831845f;   // 1/sqrt(128)
    int baserow = b * Tc;
    const float* qbase = qkv + (long)(baserow + qt * QT) * 768 + h * HDc;

    // load Q transposed: QsT[d][r]
    #pragma unroll
    for (int i = 0; i < 8; i++) {
        int idx = i * 256 + tid;
        int r = idx & 63, d4 = idx >> 6;
        float4 q = *(const float4*)(qbase + (long)r * 768 + d4 * 4);
        QsT[(d4 * 4 + 0) * QT + r] = q.x;
        QsT[(d4 * 4 + 1) * QT + r] = q.y;
        QsT[(d4 * 4 + 2) * QT + r] = q.z;
        QsT[(d4 * 4 + 3) * QT + r] = q.w;
    }

    u64 acc[4][4];   // [qi][dpair]: d = tx*8 .. tx*8+7
    #pragma unroll
    for (int i = 0; i < 4; i++)
        #pragma unroll
        for (int j = 0; j < 4; j++) acc[i][j] = 0ull;

    for (int kt = 0; kt <= qt; kt++) {
        __syncthreads();   // prev AV done (and Q visible on first iter)
        const float* kvb = qkv + (long)(baserow + kt * KT) * 768 + h * HDc;
        // K transposed
        #pragma unroll
        for (int i = 0; i < 8; i++) {
            int idx = i * 256 + tid;
            int r = idx & 63, d4 = idx >> 6;
            float4 k4 = *(const float4*)(kvb + (long)r * 768 + 256 + d4 * 4);
            KsT[(d4 * 4 + 0) * KT + r] = k4.x;
            KsT[(d4 * 4 + 1) * KT + r] = k4.y;
            KsT[(d4 * 4 + 2) * KT + r] = k4.z;
            KsT[(d4 * 4 + 3) * KT + r] = k4.w;
        }
        // V natural
        #pragma unroll
        for (int i = 0; i < 8; i++) {
            int idx = i * 256 + tid;
            int d4 = idx & 31, r = idx >> 5;
            float4 v4 = *(const float4*)(kvb + (long)r * 768 + 512 + d4 * 4);
            *(float4*)&Vs[r * HDc + d4 * 4] = v4;
        }
        __syncthreads();

        // S phase: thread (ty,tx) computes S[ty*4+qi][tx*4+kj] 4x4
        u64 s2[4][2];
        #pragma unroll
        for (int i = 0; i < 4; i++) { s2[i][0] = 0ull; s2[i][1] = 0ull; }
        #pragma unroll 8
        for (int d = 0; d < HDc; d++) {
            float4 qv = *(const float4*)&QsT[d * QT + ty * 4];
            ulonglong2 kv = *(const ulonglong2*)&KsT[d * KT + tx * 4];
            float qa[4] = {qv.x, qv.y, qv.z, qv.w};
            #pragma unroll
            for (int qi = 0; qi < 4; qi++) {
                u64 qd = dup2(qa[qi]);
                s2[qi][0] = fma2(qd, kv.x, s2[qi][0]);
                s2[qi][1] = fma2(qd, kv.y, s2[qi][1]);
            }
        }
        // scale + relu + causal mask, store to Ss[q][k]
        int kg0 = kt * KT + tx * 4;
        #pragma unroll
        for (int qi = 0; qi < 4; qi++) {
            int qg = qt * QT + ty * 4 + qi;
            float v0, v1, v2, v3;
            unpack2(s2[qi][0], v0, v1);
            unpack2(s2[qi][1], v2, v3);
            v0 = (kg0 + 0 <= qg) ? fmaxf(v0 * scale, 0.f) : 0.f;
            v1 = (kg0 + 1 <= qg) ? fmaxf(v1 * scale, 0.f) : 0.f;
            v2 = (kg0 + 2 <= qg) ? fmaxf(v2 * scale, 0.f) : 0.f;
            v3 = (kg0 + 3 <= qg) ? fmaxf(v3 * scale, 0.f) : 0.f;
            *(float4*)&Ss[(ty * 4 + qi) * 68 + tx * 4] = make_float4(v0, v1, v2, v3);
        }
        __syncthreads();

        // AV phase: q rows ty*4..+3, d cols tx*8..+7
        #pragma unroll 4
        for (int kk = 0; kk < KT; kk++) {
            ulonglong2 vv0 = *(const ulonglong2*)&Vs[kk * HDc + tx * 8];
            ulonglong2 vv1 = *(const ulonglong2*)&Vs[kk * HDc + tx * 8 + 4];
            #pragma unroll
            for (int qi = 0; qi < 4; qi++) {
                u64 sd = dup2(Ss[(ty * 4 + qi) * 68 + kk]);
                acc[qi][0] = fma2(sd, vv0.x, acc[qi][0]);
                acc[qi][1] = fma2(sd, vv0.y, acc[qi][1]);
                acc[qi][2] = fma2(sd, vv1.x, acc[qi][2]);
                acc[qi][3] = fma2(sd, vv1.y, acc[qi][3]);
            }
        }
    }

    #pragma unroll
    for (int qi = 0; qi < 4; qi++) {
        int t = qt * QT + ty * 4 + qi;
        float* yr = y + (long)(baserow + t) * Ec + h * HDc + tx * 8;
        float v0, v1, v2, v3;
        unpack2(acc[qi][0], v0, v1);
        unpack2(acc[qi][1], v2, v3);
        *(float4*)yr = make_float4(v0, v1, v2, v3);
        unpack2(acc[qi][2], v0, v1);
        unpack2(acc[qi][3], v2, v3);
        *(float4*)(yr + 4) = make_float4(v0, v1, v2, v3);
    }
}

// ---------------- mean over T: partial sums (deterministic) ----------------
__global__ void meanpart_kernel(const float* __restrict__ xf, float* __restrict__ part) {
    int c = blockIdx.x;
    int b = blockIdx.y;
    int e = threadIdx.x;
    float s = 0.f;
    for (int tt = 0; tt < 256; tt++) {
        int t = c * 256 + tt;
        s += xf[(b * Tc + t) * Ec + e];
    }
    part[(c * Bc + b) * Ec + e] = s;
}

// ---------------- final: emb, logits, losses, outputs ----------------------
__global__ void final_kernel(const float* __restrict__ part,
                             const float* __restrict__ head_w,
                             const float* __restrict__ head_b,
                             const float* __restrict__ Y,
                             float* __restrict__ out) {
    __shared__ float emb[Bc * Ec];
    __shared__ float lg[Bc * M2c];
    __shared__ float rb[8];
    int tid = threadIdx.x;

    for (int i = tid; i < Bc * Ec; i += 256) {
        int b = i >> 8, e = i & 255;
        float s = 0.f;
        #pragma unroll
        for (int c = 0; c < 8; c++) s += part[(c * Bc + b) * Ec + e];
        emb[i] = s * (1.f / Tc);
    }
    __syncthreads();

    float l1 = 0.f;
    for (int o = tid; o < Bc * M2c; o += 256) {
        int b = o / M2c, m = o % M2c;
        float s = head_b[m];
        const float* wr = head_w + m * Ec;
        const float* er = emb + b * Ec;
        #pragma unroll 4
        for (int k = 0; k < Ec; k++) s += er[k] * wr[k];
        s = fmaxf(s, 0.f);
        lg[o] = s;
        float d = s - Y[o];
        l1 += d * d;
    }
    #pragma unroll
    for (int o = 16; o; o >>= 1) l1 += __shfl_xor_sync(~0u, l1, o);
    __syncthreads();
    if ((tid & 31) == 0) rb[tid >> 5] = l1;
    __syncthreads();
    float tot1 = 0.f;
    #pragma unroll
    for (int i = 0; i < 8; i++) tot1 += rb[i];
    float loss1 = sqrtf(tot1 / (float)(Bc * M2c));

    float l3 = 0.f;
    for (int i = tid; i < Bc * (Ec / 2); i += 256) {
        int b = i / (Ec / 2), j = i % (Ec / 2);
        float e1 = emb[b * Ec + j];
        float e2 = emb[b * Ec + Ec / 2 + j];
        out[i] = e1;
        out[Bc * (Ec / 2) + i] = e2;
        float d = e1 - e2;
        l3 += d * d;
    }
    #pragma unroll
    for (int o = 16; o; o >>= 1) l3 += __shfl_xor_sync(~0u, l3, o);
    __syncthreads();
    if ((tid & 31) == 0) rb[tid >> 5] = l3;
    __syncthreads();
    float tot3 = 0.f;
    #pragma unroll
    for (int i = 0; i < 8; i++) tot3 += rb[i];
    float loss3 = sqrtf(tot3 / (float)(Bc * Ec / 2));

    int off = 2 * Bc * (Ec / 2);
    if (tid == 0) {
        out[off + 0] = 50.f * loss1 + loss3;
        out[off + 1] = loss1;
        out[off + 2] = loss3;
    }
    for (int o = tid; o < Bc * M2c; o += 256) out[off + 3 + o] = lg[o];
}

// ---------------- host launcher --------------------------------------------
extern "C" void kernel_launch(void* const* d_in, const int* in_sizes, int n_in,
                              void* d_out, int out_size) {
    const float* X          = (const float*)d_in[0];
    const float* Y          = (const float*)d_in[1];
    const float* wpe        = (const float*)d_in[2];
    const float* ln1_g      = (const float*)d_in[3];
    const float* ln1_b      = (const float*)d_in[4];
    const float* attn_w     = (const float*)d_in[5];
    const float* attn_b     = (const float*)d_in[6];
    const float* attnproj_w = (const float*)d_in[7];
    const float* attnproj_b = (const float*)d_in[8];
    const float* ln2_g      = (const float*)d_in[9];
    const float* ln2_b      = (const float*)d_in[10];
    const float* fc_w       = (const float*)d_in[11];
    const float* fc_b       = (const float*)d_in[12];
    const float* mlpproj_w  = (const float*)d_in[13];
    const float* mlpproj_b  = (const float*)d_in[14];
    const float* lnf_g      = (const float*)d_in[15];
    const float* lnf_b      = (const float*)d_in[16];
    const float* head_w     = (const float*)d_in[17];
    const float* head_b     = (const float*)d_in[18];

    float *x, *h, *qkv, *y, *fc, *part;
    cudaGetSymbolAddress((void**)&x, g_x);
    cudaGetSymbolAddress((void**)&h, g_h);
    cudaGetSymbolAddress((void**)&qkv, g_qkv);
    cudaGetSymbolAddress((void**)&y, g_y);
    cudaGetSymbolAddress((void**)&fc, g_fc);
    cudaGetSymbolAddress((void**)&part, g_part);

    cudaFuncSetAttribute(attn_kernel, cudaFuncAttributeMaxDynamicSharedMemorySize, ATTN_SMEM);

    embed_kernel<<<BT * Ec / 4 / 256, 256>>>(X, wpe, x);
    ln_kernel<<<BT, 256>>>(x, ln1_g, ln1_b, h, 0);
    gemm_kernel<<<dim3(768 / BN, BT / BM), 256>>>(h, attn_w, attn_b, nullptr, qkv, BT, 768, 256, 1, 0);
    attn_kernel<<<dim3(Tc / QT, Bc * Hc), 256, ATTN_SMEM>>>(qkv, y);
    gemm_kernel<<<dim3(256 / BN, BT / BM), 256>>>(y, attnproj_w, attnproj_b, x, x, BT, 256, 256, 0, 1);
    ln_kernel<<<BT, 256>>>(x, ln2_g, ln2_b, h, 0);
    gemm_kernel<<<dim3(512 / BN, BT / BM), 256>>>(h, fc_w, fc_b, nullptr, fc, BT, 512, 256, 1, 0);
    gemm_kernel<<<dim3(256 / BN, BT / BM), 256>>>(fc, mlpproj_w, mlpproj_b, x, x, BT, 256, 512, 1, 1);
    ln_kernel<<<BT, 256>>>(x, lnf_g, lnf_b, h, 1);
    meanpart_kernel<<<dim3(8, Bc), 256>>>(h, part);
    final_kernel<<<1, 256>>>(part, head_w, head_b, Y, (float*)d_out);
}

// round 5
// speedup vs baseline: 1.2883x; 1.1324x over previous
#include <cuda_runtime.h>
#include <math.h>

// ---------------- constants ----------------
constexpr int Bc = 8, Tc = 2048, Ec = 256, Hc = 2, HDc = 128, M2c = 134;
constexpr int BT = Bc * Tc;            // 16384 rows
constexpr int QT = 64, KT = 64;        // attention tile sizes
constexpr int NQT = Tc / QT;           // 32 q-tiles

typedef unsigned long long u64;

// packed f32x2 helpers (SASS FFMA2 — 2 fp32 FMAs per issue slot)
__device__ __forceinline__ u64 fma2(u64 a, u64 b, u64 c) {
    u64 d; asm("fma.rn.f32x2 %0, %1, %2, %3;" : "=l"(d) : "l"(a), "l"(b), "l"(c)); return d;
}
__device__ __forceinline__ u64 dup2(float x) {
    u64 d; asm("mov.b64 %0, {%1, %1};" : "=l"(d) : "f"(x)); return d;
}
__device__ __forceinline__ void unpack2(u64 v, float& lo, float& hi) {
    asm("mov.b64 {%0, %1}, %2;" : "=f"(lo), "=f"(hi) : "l"(v));
}

// ---------------- scratch (device globals; no allocations allowed) --------
__device__ float g_x[BT * Ec];
__device__ float g_h[BT * Ec];
__device__ float g_qkv[BT * 3 * Ec];
__device__ float g_y[BT * Ec];
__device__ float g_fc[BT * 2 * Ec];
__device__ float g_part[64 * Ec];

// ---------------- embed ----------------
__global__ void embed_kernel(const float* __restrict__ X,
                             const float* __restrict__ wpe,
                             float* __restrict__ out) {
    int i4 = blockIdx.x * 256 + threadIdx.x;
    int e4 = i4 & (Ec / 4 - 1);
    int t  = (i4 >> 6) & (Tc - 1);
    float4 x  = ((const float4*)X)[i4];
    float4 w  = ((const float4*)wpe)[t * (Ec / 4) + e4];
    float4 w2 = ((const float4*)wpe)[(t >= Tc / 2 ? 1 : 0) * (Ec / 4) + e4];
    float4 o;
    o.x = fmaxf(x.x + w.x + w2.x, 0.f);
    o.y = fmaxf(x.y + w.y + w2.y, 0.f);
    o.z = fmaxf(x.z + w.z + w2.z, 0.f);
    o.w = fmaxf(x.w + w.w + w2.w, 0.f);
    ((float4*)out)[i4] = o;
}

// ---------------- layernorm ----------------
__global__ void ln_kernel(const float* __restrict__ in,
                          const float* __restrict__ g,
                          const float* __restrict__ b,
                          float* __restrict__ out, int relu_out) {
    int row = blockIdx.x;
    int tid = threadIdx.x;
    __shared__ float rb[8];
    float v = in[row * Ec + tid];
    float s = v;
    #pragma unroll
    for (int o = 16; o; o >>= 1) s += __shfl_xor_sync(~0u, s, o);
    if ((tid & 31) == 0) rb[tid >> 5] = s;
    __syncthreads();
    float tot = 0;
    #pragma unroll
    for (int i = 0; i < 8; i++) tot += rb[i];
    float mu = tot * (1.f / Ec);
    float d = v - mu;
    float s2 = d * d;
    #pragma unroll
    for (int o = 16; o; o >>= 1) s2 += __shfl_xor_sync(~0u, s2, o);
    __syncthreads();
    if ((tid & 31) == 0) rb[tid >> 5] = s2;
    __syncthreads();
    float tot2 = 0;
    #pragma unroll
    for (int i = 0; i < 8; i++) tot2 += rb[i];
    float r = rsqrtf(tot2 * (1.f / Ec) + 1e-5f);
    float o = d * r * g[tid] + b[tid];
    if (relu_out) o = fmaxf(o, 0.f);
    out[row * Ec + tid] = o;
}

// ---------------- GEMM: C = act(A @ W^T + bias (+res)) ----
constexpr int BM = 128, BN = 128, BKg = 16;

__global__ void __launch_bounds__(256)
gemm_kernel(const float* __restrict__ A, const float* __restrict__ W,
            const float* __restrict__ bias, const float* __restrict__ res,
            float* __restrict__ C, int M, int N, int K, int relu, int addres) {
    __shared__ float As[BKg][BM];
    __shared__ float Bs[BKg][BN];
    int tid = threadIdx.x;
    int bm = blockIdx.y * BM, bn = blockIdx.x * BN;
    int tx = tid & 15, ty = tid >> 4;

    int lm0 = tid >> 2, lkg = tid & 3;
    int lm1 = lm0 + 64;

    u64 acc[8][4];
    #pragma unroll
    for (int i = 0; i < 8; i++)
        #pragma unroll
        for (int j = 0; j < 4; j++) acc[i][j] = 0ull;

    float4 pa0 = *(const float4*)(A + (bm + lm0) * K + lkg * 4);
    float4 pa1 = *(const float4*)(A + (bm + lm1) * K + lkg * 4);
    float4 pb0 = *(const float4*)(W + (bn + lm0) * K + lkg * 4);
    float4 pb1 = *(const float4*)(W + (bn + lm1) * K + lkg * 4);

    for (int k0 = 0; k0 < K; k0 += BKg) {
        __syncthreads();
        As[lkg * 4 + 0][lm0] = pa0.x; As[lkg * 4 + 1][lm0] = pa0.y;
        As[lkg * 4 + 2][lm0] = pa0.z; As[lkg * 4 + 3][lm0] = pa0.w;
        As[lkg * 4 + 0][lm1] = pa1.x; As[lkg * 4 + 1][lm1] = pa1.y;
        As[lkg * 4 + 2][lm1] = pa1.z; As[lkg * 4 + 3][lm1] = pa1.w;
        Bs[lkg * 4 + 0][lm0] = pb0.x; Bs[lkg * 4 + 1][lm0] = pb0.y;
        Bs[lkg * 4 + 2][lm0] = pb0.z; Bs[lkg * 4 + 3][lm0] = pb0.w;
        Bs[lkg * 4 + 0][lm1] = pb1.x; Bs[lkg * 4 + 1][lm1] = pb1.y;
        Bs[lkg * 4 + 2][lm1] = pb1.z; Bs[lkg * 4 + 3][lm1] = pb1.w;
        __syncthreads();

        if (k0 + BKg < K) {
            int kn = k0 + BKg;
            pa0 = *(const float4*)(A + (bm + lm0) * K + kn + lkg * 4);
            pa1 = *(const float4*)(A + (bm + lm1) * K + kn + lkg * 4);
            pb0 = *(const float4*)(W + (bn + lm0) * K + kn + lkg * 4);
            pb1 = *(const float4*)(W + (bn + lm1) * K + kn + lkg * 4);
        }

        #pragma unroll
        for (int kk = 0; kk < BKg; kk++) {
            float4 av0 = *(const float4*)&As[kk][ty * 4];
            float4 av1 = *(const float4*)&As[kk][ty * 4 + 64];
            ulonglong2 bv0 = *(const ulonglong2*)&Bs[kk][tx * 4];
            ulonglong2 bv1 = *(const ulonglong2*)&Bs[kk][tx * 4 + 64];
            u64 b2[4] = {bv0.x, bv0.y, bv1.x, bv1.y};
            float aa[8] = {av0.x, av0.y, av0.z, av0.w, av1.x, av1.y, av1.z, av1.w};
            #pragma unroll
            for (int i = 0; i < 8; i++) {
                u64 ad = dup2(aa[i]);
                #pragma unroll
                for (int j = 0; j < 4; j++) acc[i][j] = fma2(ad, b2[j], acc[i][j]);
            }
        }
    }

    #pragma unroll
    for (int i = 0; i < 8; i++) {
        int m = bm + (i < 4 ? ty * 4 + i : 64 + ty * 4 + i - 4);
        #pragma unroll
        for (int half = 0; half < 2; half++) {
            int n0 = bn + half * 64 + tx * 4;
            float v0, v1, v2, v3;
            unpack2(acc[i][half * 2 + 0], v0, v1);
            unpack2(acc[i][half * 2 + 1], v2, v3);
            v0 += bias[n0 + 0]; v1 += bias[n0 + 1];
            v2 += bias[n0 + 2]; v3 += bias[n0 + 3];
            if (addres) {
                const float* rr = res + m * N + n0;
                v0 += rr[0]; v1 += rr[1]; v2 += rr[2]; v3 += rr[3];
            }
            if (relu) {
                v0 = fmaxf(v0, 0.f); v1 = fmaxf(v1, 0.f);
                v2 = fmaxf(v2, 0.f); v3 = fmaxf(v3, 0.f);
            }
            *(float4*)(C + m * N + n0) = make_float4(v0, v1, v2, v3);
        }
    }
}

// ---------------- attention ---------------------------------------------
// Balanced pairing: block p handles q-tiles {NQT-1-p, p} => uniform 33 k-iters.
// Ss is ALIASED into KsT (K is dead after the S phase) -> 96KB smem,
// 2 CTAs/SM for latency hiding.
constexpr int SSP = 68;   // Ss row pitch (must be ≡ 0 mod 4 for float4 stores)
constexpr int ATTN_SMEM = (HDc * QT + HDc * KT + KT * HDc) * 4;  // 98304 B

__device__ __forceinline__ void attn_tile(const float* __restrict__ qkv,
                                          float* __restrict__ y,
                                          float* QsT, float* KsT, float* Vs,
                                          int qt, int baserow, int h,
                                          int tid, int tx, int ty) {
    const float scale = 0.08838834764831845f;   // 1/sqrt(128)
    const float* qbase = qkv + (long)(baserow + qt * QT) * 768 + h * HDc;
    float* Ss = KsT;   // alias: Ss[64][SSP] fits in KsT's 8192 floats (64*68=4352)

    // load Q transposed: QsT[d][r]
    #pragma unroll
    for (int i = 0; i < 8; i++) {
        int idx = i * 256 + tid;
        int r = idx & 63, d4 = idx >> 6;
        float4 q = *(const float4*)(qbase + (long)r * 768 + d4 * 4);
        QsT[(d4 * 4 + 0) * QT + r] = q.x;
        QsT[(d4 * 4 + 1) * QT + r] = q.y;
        QsT[(d4 * 4 + 2) * QT + r] = q.z;
        QsT[(d4 * 4 + 3) * QT + r] = q.w;
    }

    u64 acc[4][4];
    #pragma unroll
    for (int i = 0; i < 4; i++)
        #pragma unroll
        for (int j = 0; j < 4; j++) acc[i][j] = 0ull;

    for (int kt = 0; kt <= qt; kt++) {
        __syncthreads();   // prev AV done reading Ss(=KsT)/Vs; QsT visible (1st iter)
        const float* kvb = qkv + (long)(baserow + kt * KT) * 768 + h * HDc;
        #pragma unroll
        for (int i = 0; i < 8; i++) {
            int idx = i * 256 + tid;
            int r = idx & 63, d4 = idx >> 6;
            float4 k4 = *(const float4*)(kvb + (long)r * 768 + 256 + d4 * 4);
            KsT[(d4 * 4 + 0) * KT + r] = k4.x;
            KsT[(d4 * 4 + 1) * KT + r] = k4.y;
            KsT[(d4 * 4 + 2) * KT + r] = k4.z;
            KsT[(d4 * 4 + 3) * KT + r] = k4.w;
        }
        #pragma unroll
        for (int i = 0; i < 8; i++) {
            int idx = i * 256 + tid;
            int d4 = idx & 31, r = idx >> 5;
            float4 v4 = *(const float4*)(kvb + (long)r * 768 + 512 + d4 * 4);
            *(float4*)&Vs[r * HDc + d4 * 4] = v4;
        }
        __syncthreads();

        // S phase: (ty,tx) -> S[ty*4+qi][tx*4+kj], held in registers
        u64 s2[4][2];
        #pragma unroll
        for (int i = 0; i < 4; i++) { s2[i][0] = 0ull; s2[i][1] = 0ull; }
        #pragma unroll 8
        for (int d = 0; d < HDc; d++) {
            float4 qv = *(const float4*)&QsT[d * QT + ty * 4];
            ulonglong2 kv = *(const ulonglong2*)&KsT[d * KT + tx * 4];
            float qa[4] = {qv.x, qv.y, qv.z, qv.w};
            #pragma unroll
            for (int qi = 0; qi < 4; qi++) {
                u64 qd = dup2(qa[qi]);
                s2[qi][0] = fma2(qd, kv.x, s2[qi][0]);
                s2[qi][1] = fma2(qd, kv.y, s2[qi][1]);
            }
        }
        __syncthreads();   // all KsT reads done; safe to overwrite with Ss

        int kg0 = kt * KT + tx * 4;
        #pragma unroll
        for (int qi = 0; qi < 4; qi++) {
            int qg = qt * QT + ty * 4 + qi;
            float v0, v1, v2, v3;
            unpack2(s2[qi][0], v0, v1);
            unpack2(s2[qi][1], v2, v3);
            v0 = (kg0 + 0 <= qg) ? fmaxf(v0 * scale, 0.f) : 0.f;
            v1 = (kg0 + 1 <= qg) ? fmaxf(v1 * scale, 0.f) : 0.f;
            v2 = (kg0 + 2 <= qg) ? fmaxf(v2 * scale, 0.f) : 0.f;
            v3 = (kg0 + 3 <= qg) ? fmaxf(v3 * scale, 0.f) : 0.f;
            *(float4*)&Ss[(ty * 4 + qi) * SSP + tx * 4] = make_float4(v0, v1, v2, v3);
        }
        __syncthreads();   // Ss visible

        // AV phase: q rows ty*4..+3, d cols tx*8..+7
        #pragma unroll 4
        for (int kk = 0; kk < KT; kk++) {
            ulonglong2 vv0 = *(const ulonglong2*)&Vs[kk * HDc + tx * 8];
            ulonglong2 vv1 = *(const ulonglong2*)&Vs[kk * HDc + tx * 8 + 4];
            #pragma unroll
            for (int qi = 0; qi < 4; qi++) {
                u64 sd = dup2(Ss[(ty * 4 + qi) * SSP + kk]);
                acc[qi][0] = fma2(sd, vv0.x, acc[qi][0]);
                acc[qi][1] = fma2(sd, vv0.y, acc[qi][1]);
                acc[qi][2] = fma2(sd, vv1.x, acc[qi][2]);
                acc[qi][3] = fma2(sd, vv1.y, acc[qi][3]);
            }
        }
    }

    #pragma unroll
    for (int qi = 0; qi < 4; qi++) {
        int t = qt * QT + ty * 4 + qi;
        float* yr = y + (long)(baserow + t) * Ec + h * HDc + tx * 8;
        float v0, v1, v2, v3;
        unpack2(acc[qi][0], v0, v1);
        unpack2(acc[qi][1], v2, v3);
        *(float4*)yr = make_float4(v0, v1, v2, v3);
        unpack2(acc[qi][2], v0, v1);
        unpack2(acc[qi][3], v2, v3);
        *(float4*)(yr + 4) = make_float4(v0, v1, v2, v3);
    }
}

__global__ void __launch_bounds__(256, 2)
attn_kernel(const float* __restrict__ qkv, float* __restrict__ y) {
    extern __shared__ float sm[];
    float* QsT = sm;
    float* KsT = QsT + HDc * QT;
    float* Vs  = KsT + HDc * KT;

    int pair = blockIdx.x;     // 0..NQT/2-1
    int bh = blockIdx.y;
    int b = bh >> 1, h = bh & 1;
    int tid = threadIdx.x;
    int tx = tid & 15, ty = tid >> 4;
    int baserow = b * Tc;

    // heavy tile first, then light tile: 33 k-iterations total per block
    attn_tile(qkv, y, QsT, KsT, Vs, NQT - 1 - pair, baserow, h, tid, tx, ty);
    __syncthreads();   // tile boundary: all reads of Vs/Ss done before reuse
    attn_tile(qkv, y, QsT, KsT, Vs, pair,           baserow, h, tid, tx, ty);
}

// ---------------- mean over T ----------------
__global__ void meanpart_kernel(const float* __restrict__ xf, float* __restrict__ part) {
    int c = blockIdx.x;
    int b = blockIdx.y;
    int e = threadIdx.x;
    float s = 0.f;
    for (int tt = 0; tt < 256; tt++) {
        int t = c * 256 + tt;
        s += xf[(b * Tc + t) * Ec + e];
    }
    part[(c * Bc + b) * Ec + e] = s;
}

// ---------------- final ----------------
__global__ void final_kernel(const float* __restrict__ part,
                             const float* __restrict__ head_w,
                             const float* __restrict__ head_b,
                             const float* __restrict__ Y,
                             float* __restrict__ out) {
    __shared__ float emb[Bc * Ec];
    __shared__ float lg[Bc * M2c];
    __shared__ float rb[8];
    int tid = threadIdx.x;

    for (int i = tid; i < Bc * Ec; i += 256) {
        int b = i >> 8, e = i & 255;
        float s = 0.f;
        #pragma unroll
        for (int c = 0; c < 8; c++) s += part[(c * Bc + b) * Ec + e];
        emb[i] = s * (1.f / Tc);
    }
    __syncthreads();

    float l1 = 0.f;
    for (int o = tid; o < Bc * M2c; o += 256) {
        int b = o / M2c, m = o % M2c;
        float s = head_b[m];
        const float* wr = head_w + m * Ec;
        const float* er = emb + b * Ec;
        #pragma unroll 4
        for (int k = 0; k < Ec; k++) s += er[k] * wr[k];
        s = fmaxf(s, 0.f);
        lg[o] = s;
        float d = s - Y[o];
        l1 += d * d;
    }
    #pragma unroll
    for (int o = 16; o; o >>= 1) l1 += __shfl_xor_sync(~0u, l1, o);
    __syncthreads();
    if ((tid & 31) == 0) rb[tid >> 5] = l1;
    __syncthreads();
    float tot1 = 0.f;
    #pragma unroll
    for (int i = 0; i < 8; i++) tot1 += rb[i];
    float loss1 = sqrtf(tot1 / (float)(Bc * M2c));

    float l3 = 0.f;
    for (int i = tid; i < Bc * (Ec / 2); i += 256) {
        int b = i / (Ec / 2), j = i % (Ec / 2);
        float e1 = emb[b * Ec + j];
        float e2 = emb[b * Ec + Ec / 2 + j];
        out[i] = e1;
        out[Bc * (Ec / 2) + i] = e2;
        float d = e1 - e2;
        l3 += d * d;
    }
    #pragma unroll
    for (int o = 16; o; o >>= 1) l3 += __shfl_xor_sync(~0u, l3, o);
    __syncthreads();
    if ((tid & 31) == 0) rb[tid >> 5] = l3;
    __syncthreads();
    float tot3 = 0.f;
    #pragma unroll
    for (int i = 0; i < 8; i++) tot3 += rb[i];
    float loss3 = sqrtf(tot3 / (float)(Bc * Ec / 2));

    int off = 2 * Bc * (Ec / 2);
    if (tid == 0) {
        out[off + 0] = 50.f * loss1 + loss3;
        out[off + 1] = loss1;
        out[off + 2] = loss3;
    }
    for (int o = tid; o < Bc * M2c; o += 256) out[off + 3 + o] = lg[o];
}

// ---------------- host launcher ----------------
extern "C" void kernel_launch(void* const* d_in, const int* in_sizes, int n_in,
                              void* d_out, int out_size) {
    const float* X          = (const float*)d_in[0];
    const float* Y          = (const float*)d_in[1];
    const float* wpe        = (const float*)d_in[2];
    const float* ln1_g      = (const float*)d_in[3];
    const float* ln1_b      = (const float*)d_in[4];
    const float* attn_w     = (const float*)d_in[5];
    const float* attn_b     = (const float*)d_in[6];
    const float* attnproj_w = (const float*)d_in[7];
    const float* attnproj_b = (const float*)d_in[8];
    const float* ln2_g      = (const float*)d_in[9];
    const float* ln2_b      = (const float*)d_in[10];
    const float* fc_w       = (const float*)d_in[11];
    const float* fc_b       = (const float*)d_in[12];
    const float* mlpproj_w  = (const float*)d_in[13];
    const float* mlpproj_b  = (const float*)d_in[14];
    const float* lnf_g      = (const float*)d_in[15];
    const float* lnf_b      = (const float*)d_in[16];
    const float* head_w     = (const float*)d_in[17];
    const float* head_b     = (const float*)d_in[18];

    float *x, *h, *qkv, *y, *fc, *part;
    cudaGetSymbolAddress((void**)&x, g_x);
    cudaGetSymbolAddress((void**)&h, g_h);
    cudaGetSymbolAddress((void**)&qkv, g_qkv);
    cudaGetSymbolAddress((void**)&y, g_y);
    cudaGetSymbolAddress((void**)&fc, g_fc);
    cudaGetSymbolAddress((void**)&part, g_part);

    cudaFuncSetAttribute(attn_kernel, cudaFuncAttributeMaxDynamicSharedMemorySize, ATTN_SMEM);
    cudaFuncSetAttribute(attn_kernel, cudaFuncAttributePreferredSharedMemoryCarveout,
                         cudaSharedmemCarveoutMaxShared);

    embed_kernel<<<BT * Ec / 4 / 256, 256>>>(X, wpe, x);
    ln_kernel<<<BT, 256>>>(x, ln1_g, ln1_b, h, 0);
    gemm_kernel<<<dim3(768 / BN, BT / BM), 256>>>(h, attn_w, attn_b, nullptr, qkv, BT, 768, 256, 1, 0);
    attn_kernel<<<dim3(NQT / 2, Bc * Hc), 256, ATTN_SMEM>>>(qkv, y);
    gemm_kernel<<<dim3(256 / BN, BT / BM), 256>>>(y, attnproj_w, attnproj_b, x, x, BT, 256, 256, 0, 1);
    ln_kernel<<<BT, 256>>>(x, ln2_g, ln2_b, h, 0);
    gemm_kernel<<<dim3(512 / BN, BT / BM), 256>>>(h, fc_w, fc_b, nullptr, fc, BT, 512, 256, 1, 0);
    gemm_kernel<<<dim3(256 / BN, BT / BM), 256>>>(fc, mlpproj_w, mlpproj_b, x, x, BT, 256, 512, 1, 1);
    ln_kernel<<<BT, 256>>>(x, lnf_g, lnf_b, h, 1);
    meanpart_kernel<<<dim3(8, Bc), 256>>>(h, part);
    final_kernel<<<1, 256>>>(part, head_w, head_b, Y, (float*)d_out);
}

// round 6
// speedup vs baseline: 2.0593x; 1.5985x over previous
#include <cuda_runtime.h>
#include <math.h>

// ---------------- constants ----------------
constexpr int Bc = 8, Tc = 2048, Ec = 256, Hc = 2, HDc = 128, M2c = 134;
constexpr int BT = Bc * Tc;            // 16384 rows
constexpr int QT2 = 128, KT2 = 128;    // attention tile sizes (tensor-core path)
constexpr int NQT2 = Tc / QT2;         // 16 q-tiles
constexpr int P = 132;                 // smem pitch (floats) — conflict-free fragments

typedef unsigned long long u64;

// packed f32x2 helpers (SASS FFMA2) — used by the SIMT GEMM
__device__ __forceinline__ u64 fma2(u64 a, u64 b, u64 c) {
    u64 d; asm("fma.rn.f32x2 %0, %1, %2, %3;" : "=l"(d) : "l"(a), "l"(b), "l"(c)); return d;
}
__device__ __forceinline__ u64 dup2(float x) {
    u64 d; asm("mov.b64 %0, {%1, %1};" : "=l"(d) : "f"(x)); return d;
}
__device__ __forceinline__ void unpack2(u64 v, float& lo, float& hi) {
    asm("mov.b64 {%0, %1}, %2;" : "=f"(lo), "=f"(hi) : "l"(v));
}

// tf32 helpers
__device__ __forceinline__ unsigned f2tf(float f) {
    unsigned u; asm("cvt.rna.tf32.f32 %0, %1;" : "=r"(u) : "f"(f)); return u;
}
__device__ __forceinline__ void mma8(float c[4], const unsigned a[4], const unsigned b[2]) {
    asm volatile("mma.sync.aligned.m16n8k8.row.col.f32.tf32.tf32.f32 "
        "{%0,%1,%2,%3},{%4,%5,%6,%7},{%8,%9},{%0,%1,%2,%3};"
        : "+f"(c[0]), "+f"(c[1]), "+f"(c[2]), "+f"(c[3])
        : "r"(a[0]), "r"(a[1]), "r"(a[2]), "r"(a[3]), "r"(b[0]), "r"(b[1]));
}

// ---------------- scratch (device globals; no allocations allowed) --------
__device__ float g_x[BT * Ec];
__device__ float g_h[BT * Ec];
__device__ float g_qkv[BT * 3 * Ec];
__device__ float g_y[BT * Ec];
__device__ float g_fc[BT * 2 * Ec];
__device__ float g_part[64 * Ec];

// ---------------- embed ----------------
__global__ void embed_kernel(const float* __restrict__ X,
                             const float* __restrict__ wpe,
                             float* __restrict__ out) {
    int i4 = blockIdx.x * 256 + threadIdx.x;
    int e4 = i4 & (Ec / 4 - 1);
    int t  = (i4 >> 6) & (Tc - 1);
    float4 x  = ((const float4*)X)[i4];
    float4 w  = ((const float4*)wpe)[t * (Ec / 4) + e4];
    float4 w2 = ((const float4*)wpe)[(t >= Tc / 2 ? 1 : 0) * (Ec / 4) + e4];
    float4 o;
    o.x = fmaxf(x.x + w.x + w2.x, 0.f);
    o.y = fmaxf(x.y + w.y + w2.y, 0.f);
    o.z = fmaxf(x.z + w.z + w2.z, 0.f);
    o.w = fmaxf(x.w + w.w + w2.w, 0.f);
    ((float4*)out)[i4] = o;
}

// ---------------- layernorm ----------------
__global__ void ln_kernel(const float* __restrict__ in,
                          const float* __restrict__ g,
                          const float* __restrict__ b,
                          float* __restrict__ out, int relu_out) {
    int row = blockIdx.x;
    int tid = threadIdx.x;
    __shared__ float rb[8];
    float v = in[row * Ec + tid];
    float s = v;
    #pragma unroll
    for (int o = 16; o; o >>= 1) s += __shfl_xor_sync(~0u, s, o);
    if ((tid & 31) == 0) rb[tid >> 5] = s;
    __syncthreads();
    float tot = 0;
    #pragma unroll
    for (int i = 0; i < 8; i++) tot += rb[i];
    float mu = tot * (1.f / Ec);
    float d = v - mu;
    float s2 = d * d;
    #pragma unroll
    for (int o = 16; o; o >>= 1) s2 += __shfl_xor_sync(~0u, s2, o);
    __syncthreads();
    if ((tid & 31) == 0) rb[tid >> 5] = s2;
    __syncthreads();
    float tot2 = 0;
    #pragma unroll
    for (int i = 0; i < 8; i++) tot2 += rb[i];
    float r = rsqrtf(tot2 * (1.f / Ec) + 1e-5f);
    float o = d * r * g[tid] + b[tid];
    if (relu_out) o = fmaxf(o, 0.f);
    out[row * Ec + tid] = o;
}

// ---------------- GEMM: C = act(A @ W^T + bias (+res)) — FFMA2 SIMT ----
constexpr int BM = 128, BN = 128, BKg = 16;

__global__ void __launch_bounds__(256)
gemm_kernel(const float* __restrict__ A, const float* __restrict__ W,
            const float* __restrict__ bias, const float* __restrict__ res,
            float* __restrict__ C, int M, int N, int K, int relu, int addres) {
    __shared__ float As[BKg][BM];
    __shared__ float Bs[BKg][BN];
    int tid = threadIdx.x;
    int bm = blockIdx.y * BM, bn = blockIdx.x * BN;
    int tx = tid & 15, ty = tid >> 4;

    int lm0 = tid >> 2, lkg = tid & 3;
    int lm1 = lm0 + 64;

    u64 acc[8][4];
    #pragma unroll
    for (int i = 0; i < 8; i++)
        #pragma unroll
        for (int j = 0; j < 4; j++) acc[i][j] = 0ull;

    float4 pa0 = *(const float4*)(A + (bm + lm0) * K + lkg * 4);
    float4 pa1 = *(const float4*)(A + (bm + lm1) * K + lkg * 4);
    float4 pb0 = *(const float4*)(W + (bn + lm0) * K + lkg * 4);
    float4 pb1 = *(const float4*)(W + (bn + lm1) * K + lkg * 4);

    for (int k0 = 0; k0 < K; k0 += BKg) {
        __syncthreads();
        As[lkg * 4 + 0][lm0] = pa0.x; As[lkg * 4 + 1][lm0] = pa0.y;
        As[lkg * 4 + 2][lm0] = pa0.z; As[lkg * 4 + 3][lm0] = pa0.w;
        As[lkg * 4 + 0][lm1] = pa1.x; As[lkg * 4 + 1][lm1] = pa1.y;
        As[lkg * 4 + 2][lm1] = pa1.z; As[lkg * 4 + 3][lm1] = pa1.w;
        Bs[lkg * 4 + 0][lm0] = pb0.x; Bs[lkg * 4 + 1][lm0] = pb0.y;
        Bs[lkg * 4 + 2][lm0] = pb0.z; Bs[lkg * 4 + 3][lm0] = pb0.w;
        Bs[lkg * 4 + 0][lm1] = pb1.x; Bs[lkg * 4 + 1][lm1] = pb1.y;
        Bs[lkg * 4 + 2][lm1] = pb1.z; Bs[lkg * 4 + 3][lm1] = pb1.w;
        __syncthreads();

        if (k0 + BKg < K) {
            int kn = k0 + BKg;
            pa0 = *(const float4*)(A + (bm + lm0) * K + kn + lkg * 4);
            pa1 = *(const float4*)(A + (bm + lm1) * K + kn + lkg * 4);
            pb0 = *(const float4*)(W + (bn + lm0) * K + kn + lkg * 4);
            pb1 = *(const float4*)(W + (bn + lm1) * K + kn + lkg * 4);
        }

        #pragma unroll
        for (int kk = 0; kk < BKg; kk++) {
            float4 av0 = *(const float4*)&As[kk][ty * 4];
            float4 av1 = *(const float4*)&As[kk][ty * 4 + 64];
            ulonglong2 bv0 = *(const ulonglong2*)&Bs[kk][tx * 4];
            ulonglong2 bv1 = *(const ulonglong2*)&Bs[kk][tx * 4 + 64];
            u64 b2[4] = {bv0.x, bv0.y, bv1.x, bv1.y};
            float aa[8] = {av0.x, av0.y, av0.z, av0.w, av1.x, av1.y, av1.z, av1.w};
            #pragma unroll
            for (int i = 0; i < 8; i++) {
                u64 ad = dup2(aa[i]);
                #pragma unroll
                for (int j = 0; j < 4; j++) acc[i][j] = fma2(ad, b2[j], acc[i][j]);
            }
        }
    }

    #pragma unroll
    for (int i = 0; i < 8; i++) {
        int m = bm + (i < 4 ? ty * 4 + i : 64 + ty * 4 + i - 4);
        #pragma unroll
        for (int half = 0; half < 2; half++) {
            int n0 = bn + half * 64 + tx * 4;
            float v0, v1, v2, v3;
            unpack2(acc[i][half * 2 + 0], v0, v1);
            unpack2(acc[i][half * 2 + 1], v2, v3);
            v0 += bias[n0 + 0]; v1 += bias[n0 + 1];
            v2 += bias[n0 + 2]; v3 += bias[n0 + 3];
            if (addres) {
                const float* rr = res + m * N + n0;
                v0 += rr[0]; v1 += rr[1]; v2 += rr[2]; v3 += rr[3];
            }
            if (relu) {
                v0 = fmaxf(v0, 0.f); v1 = fmaxf(v1, 0.f);
                v2 = fmaxf(v2, 0.f); v3 = fmaxf(v3, 0.f);
            }
            *(float4*)(C + m * N + n0) = make_float4(v0, v1, v2, v3);
        }
    }
}

// ---------------- attention: tf32 mma.sync (m16n8k8) ----------------------
// 128x128 tiles; 8 warps = 4(q-strip of 32) x 2(64-col strip); S aliased
// over Ks; causal pairing => 128 uniform blocks, single wave.
constexpr int ATTN_SMEM = 3 * 128 * P * 4;   // 202752 B

// gmem [128 rows x 128 cols], row stride 768 -> smem tf32 [row][col] pitch P
__device__ __forceinline__ void load_tile_tf32(const float* __restrict__ src,
                                               unsigned* dst, int tid) {
    #pragma unroll
    for (int i = 0; i < 16; i++) {
        int idx = i * 256 + tid;
        int d4 = idx & 31, r = idx >> 5;
        float4 v = *(const float4*)(src + (long)r * 768 + d4 * 4);
        uint4 u = make_uint4(f2tf(v.x), f2tf(v.y), f2tf(v.z), f2tf(v.w));
        *(uint4*)(dst + r * P + d4 * 4) = u;
    }
}

__device__ __forceinline__ void attn_tile(const float* __restrict__ qkv,
                                          float* __restrict__ y,
                                          unsigned* Qs, unsigned* Ks, unsigned* Vs,
                                          int qt, int baserow, int h, int tid) {
    const float scale = 0.08838834764831845f;   // 1/sqrt(128)
    int lane = tid & 31, wid = tid >> 5;
    int g = lane >> 2, tig = lane & 3;
    int wm = wid >> 1, wn = wid & 1;
    unsigned* Ss = Ks;   // alias: S[128][P] over K's region (dead after S phase)

    load_tile_tf32(qkv + (long)(baserow + qt * QT2) * 768 + h * HDc, Qs, tid);

    float yacc[2][8][4];
    #pragma unroll
    for (int ma = 0; ma < 2; ma++)
        #pragma unroll
        for (int na = 0; na < 8; na++)
            #pragma unroll
            for (int r = 0; r < 4; r++) yacc[ma][na][r] = 0.f;

    for (int kt = 0; kt <= qt; kt++) {
        __syncthreads();   // prev AV reads of Ss/Vs done; Qs visible (1st iter)
        const float* kvb = qkv + (long)(baserow + kt * KT2) * 768 + h * HDc;
        load_tile_tf32(kvb + 256, Ks, tid);
        load_tile_tf32(kvb + 512, Vs, tid);
        __syncthreads();

        // ---- S = Q @ K^T ----
        float sacc[2][8][4];
        #pragma unroll
        for (int ma = 0; ma < 2; ma++)
            #pragma unroll
            for (int na = 0; na < 8; na++)
                #pragma unroll
                for (int r = 0; r < 4; r++) sacc[ma][na][r] = 0.f;

        #pragma unroll 4
        for (int ks = 0; ks < 16; ks++) {
            int d0 = ks * 8;
            unsigned a[2][4];
            #pragma unroll
            for (int ma = 0; ma < 2; ma++) {
                int qr = wm * 32 + ma * 16;
                a[ma][0] = Qs[(qr + g) * P + d0 + tig];
                a[ma][1] = Qs[(qr + g + 8) * P + d0 + tig];
                a[ma][2] = Qs[(qr + g) * P + d0 + tig + 4];
                a[ma][3] = Qs[(qr + g + 8) * P + d0 + tig + 4];
            }
            #pragma unroll
            for (int na = 0; na < 8; na++) {
                int kc = wn * 64 + na * 8 + g;
                unsigned b[2] = { Ks[kc * P + d0 + tig], Ks[kc * P + d0 + tig + 4] };
                mma8(sacc[0][na], a[0], b);
                mma8(sacc[1][na], a[1], b);
            }
        }
        __syncthreads();   // all Ks reads done; Ss may overwrite

        // ---- scale + relu + causal mask; store S (tf32) ----
        #pragma unroll
        for (int ma = 0; ma < 2; ma++)
            #pragma unroll
            for (int na = 0; na < 8; na++) {
                int lq0 = wm * 32 + ma * 16 + g;
                int lk  = wn * 64 + na * 8 + 2 * tig;
                int qg0 = qt * QT2 + lq0, qg1 = qg0 + 8;
                int kg  = kt * KT2 + lk;
                float* c = sacc[ma][na];
                float v0 = (kg     <= qg0) ? fmaxf(c[0] * scale, 0.f) : 0.f;
                float v1 = (kg + 1 <= qg0) ? fmaxf(c[1] * scale, 0.f) : 0.f;
                float v2 = (kg     <= qg1) ? fmaxf(c[2] * scale, 0.f) : 0.f;
                float v3 = (kg + 1 <= qg1) ? fmaxf(c[3] * scale, 0.f) : 0.f;
                *(uint2*)(Ss + lq0 * P + lk)       = make_uint2(f2tf(v0), f2tf(v1));
                *(uint2*)(Ss + (lq0 + 8) * P + lk) = make_uint2(f2tf(v2), f2tf(v3));
            }
        __syncthreads();   // Ss visible

        // ---- Y += S @ V ----
        #pragma unroll 4
        for (int ks = 0; ks < 16; ks++) {
            int kp0 = ks * 8;
            unsigned a[2][4];
            #pragma unroll
            for (int ma = 0; ma < 2; ma++) {
                int qr = wm * 32 + ma * 16;
                a[ma][0] = Ss[(qr + g) * P + kp0 + tig];
                a[ma][1] = Ss[(qr + g + 8) * P + kp0 + tig];
                a[ma][2] = Ss[(qr + g) * P + kp0 + tig + 4];
                a[ma][3] = Ss[(qr + g + 8) * P + kp0 + tig + 4];
            }
            #pragma unroll
            for (int na = 0; na < 8; na++) {
                int dc = wn * 64 + na * 8 + g;
                unsigned b[2] = { Vs[(kp0 + tig) * P + dc], Vs[(kp0 + tig + 4) * P + dc] };
                mma8(yacc[0][na], a[0], b);
                mma8(yacc[1][na], a[1], b);
            }
        }
    }

    // ---- write y ----
    #pragma unroll
    for (int ma = 0; ma < 2; ma++)
        #pragma unroll
        for (int na = 0; na < 8; na++) {
            int row0 = baserow + qt * QT2 + wm * 32 + ma * 16 + g;
            int col  = h * HDc + wn * 64 + na * 8 + 2 * tig;
            float* c = yacc[ma][na];
            *(float2*)(y + (long)row0 * Ec + col)       = make_float2(c[0], c[1]);
            *(float2*)(y + (long)(row0 + 8) * Ec + col) = make_float2(c[2], c[3]);
        }
}

__global__ void __launch_bounds__(256, 1)
attn_kernel(const float* __restrict__ qkv, float* __restrict__ y) {
    extern __shared__ unsigned smu[];
    unsigned* Qs = smu;
    unsigned* Ks = smu + 128 * P;
    unsigned* Vs = smu + 2 * 128 * P;

    int pair = blockIdx.x;     // 0..NQT2/2-1
    int bh = blockIdx.y;
    int b = bh >> 1, h = bh & 1;
    int baserow = b * Tc;

    // heavy tile then light tile: uniform 17 k-iterations per block
    attn_tile(qkv, y, Qs, Ks, Vs, NQT2 - 1 - pair, baserow, h, threadIdx.x);
    __syncthreads();
    attn_tile(qkv, y, Qs, Ks, Vs, pair, baserow, h, threadIdx.x);
}

// ---------------- mean over T ----------------
__global__ void meanpart_kernel(const float* __restrict__ xf, float* __restrict__ part) {
    int c = blockIdx.x;
    int b = blockIdx.y;
    int e = threadIdx.x;
    float s = 0.f;
    for (int tt = 0; tt < 256; tt++) {
        int t = c * 256 + tt;
        s += xf[(b * Tc + t) * Ec + e];
    }
    part[(c * Bc + b) * Ec + e] = s;
}

// ---------------- final ----------------
__global__ void final_kernel(const float* __restrict__ part,
                             const float* __restrict__ head_w,
                             const float* __restrict__ head_b,
                             const float* __restrict__ Y,
                             float* __restrict__ out) {
    __shared__ float emb[Bc * Ec];
    __shared__ float lg[Bc * M2c];
    __shared__ float rb[8];
    int tid = threadIdx.x;

    for (int i = tid; i < Bc * Ec; i += 256) {
        int b = i >> 8, e = i & 255;
        float s = 0.f;
        #pragma unroll
        for (int c = 0; c < 8; c++) s += part[(c * Bc + b) * Ec + e];
        emb[i] = s * (1.f / Tc);
    }
    __syncthreads();

    float l1 = 0.f;
    for (int o = tid; o < Bc * M2c; o += 256) {
        int b = o / M2c, m = o % M2c;
        float s = head_b[m];
        const float* wr = head_w + m * Ec;
        const float* er = emb + b * Ec;
        #pragma unroll 4
        for (int k = 0; k < Ec; k++) s += er[k] * wr[k];
        s = fmaxf(s, 0.f);
        lg[o] = s;
        float d = s - Y[o];
        l1 += d * d;
    }
    #pragma unroll
    for (int o = 16; o; o >>= 1) l1 += __shfl_xor_sync(~0u, l1, o);
    __syncthreads();
    if ((tid & 31) == 0) rb[tid >> 5] = l1;
    __syncthreads();
    float tot1 = 0.f;
    #pragma unroll
    for (int i = 0; i < 8; i++) tot1 += rb[i];
    float loss1 = sqrtf(tot1 / (float)(Bc * M2c));

    float l3 = 0.f;
    for (int i = tid; i < Bc * (Ec / 2); i += 256) {
        int b = i / (Ec / 2), j = i % (Ec / 2);
        float e1 = emb[b * Ec + j];
        float e2 = emb[b * Ec + Ec / 2 + j];
        out[i] = e1;
        out[Bc * (Ec / 2) + i] = e2;
        float d = e1 - e2;
        l3 += d * d;
    }
    #pragma unroll
    for (int o = 16; o; o >>= 1) l3 += __shfl_xor_sync(~0u, l3, o);
    __syncthreads();
    if ((tid & 31) == 0) rb[tid >> 5] = l3;
    __syncthreads();
    float tot3 = 0.f;
    #pragma unroll
    for (int i = 0; i < 8; i++) tot3 += rb[i];
    float loss3 = sqrtf(tot3 / (float)(Bc * Ec / 2));

    int off = 2 * Bc * (Ec / 2);
    if (tid == 0) {
        out[off + 0] = 50.f * loss1 + loss3;
        out[off + 1] = loss1;
        out[off + 2] = loss3;
    }
    for (int o = tid; o < Bc * M2c; o += 256) out[off + 3 + o] = lg[o];
}

// ---------------- host launcher ----------------
extern "C" void kernel_launch(void* const* d_in, const int* in_sizes, int n_in,
                              void* d_out, int out_size) {
    const float* X          = (const float*)d_in[0];
    const float* Y          = (const float*)d_in[1];
    const float* wpe        = (const float*)d_in[2];
    const float* ln1_g      = (const float*)d_in[3];
    const float* ln1_b      = (const float*)d_in[4];
    const float* attn_w     = (const float*)d_in[5];
    const float* attn_b     = (const float*)d_in[6];
    const float* attnproj_w = (const float*)d_in[7];
    const float* attnproj_b = (const float*)d_in[8];
    const float* ln2_g      = (const float*)d_in[9];
    const float* ln2_b      = (const float*)d_in[10];
    const float* fc_w       = (const float*)d_in[11];
    const float* fc_b       = (const float*)d_in[12];
    const float* mlpproj_w  = (const float*)d_in[13];
    const float* mlpproj_b  = (const float*)d_in[14];
    const float* lnf_g      = (const float*)d_in[15];
    const float* lnf_b      = (const float*)d_in[16];
    const float* head_w     = (const float*)d_in[17];
    const float* head_b     = (const float*)d_in[18];

    float *x, *h, *qkv, *y, *fc, *part;
    cudaGetSymbolAddress((void**)&x, g_x);
    cudaGetSymbolAddress((void**)&h, g_h);
    cudaGetSymbolAddress((void**)&qkv, g_qkv);
    cudaGetSymbolAddress((void**)&y, g_y);
    cudaGetSymbolAddress((void**)&fc, g_fc);
    cudaGetSymbolAddress((void**)&part, g_part);

    cudaFuncSetAttribute(attn_kernel, cudaFuncAttributeMaxDynamicSharedMemorySize, ATTN_SMEM);
    cudaFuncSetAttribute(attn_kernel, cudaFuncAttributePreferredSharedMemoryCarveout,
                         cudaSharedmemCarveoutMaxShared);

    embed_kernel<<<BT * Ec / 4 / 256, 256>>>(X, wpe, x);
    ln_kernel<<<BT, 256>>>(x, ln1_g, ln1_b, h, 0);
    gemm_kernel<<<dim3(768 / BN, BT / BM), 256>>>(h, attn_w, attn_b, nullptr, qkv, BT, 768, 256, 1, 0);
    attn_kernel<<<dim3(NQT2 / 2, Bc * Hc), 256, ATTN_SMEM>>>(qkv, y);
    gemm_kernel<<<dim3(256 / BN, BT / BM), 256>>>(y, attnproj_w, attnproj_b, x, x, BT, 256, 256, 0, 1);
    ln_kernel<<<BT, 256>>>(x, ln2_g, ln2_b, h, 0);
    gemm_kernel<<<dim3(512 / BN, BT / BM), 256>>>(h, fc_w, fc_b, nullptr, fc, BT, 512, 256, 1, 0);
    gemm_kernel<<<dim3(256 / BN, BT / BM), 256>>>(fc, mlpproj_w, mlpproj_b, x, x, BT, 256, 512, 1, 1);
    ln_kernel<<<BT, 256>>>(x, lnf_g, lnf_b, h, 1);
    meanpart_kernel<<<dim3(8, Bc), 256>>>(h, part);
    final_kernel<<<1, 256>>>(part, head_w, head_b, Y, (float*)d_out);
}

// round 7
// speedup vs baseline: 3.0395x; 1.4760x over previous
#include <cuda_runtime.h>
#include <math.h>

// ---------------- constants ----------------
constexpr int Bc = 8, Tc = 2048, Ec = 256, Hc = 2, HDc = 128, M2c = 134;
constexpr int BT = Bc * Tc;            // 16384 rows
constexpr int QT2 = 128, KT2 = 128;    // attention tile sizes
constexpr int NQT2 = Tc / QT2;         // 16 q-tiles
constexpr int P = 132;                 // attn smem pitch
constexpr int GP = 68;                 // gemm smem pitch (64-wide chunks)

// tf32 helpers
__device__ __forceinline__ unsigned f2tf(float f) {
    unsigned u; asm("cvt.rna.tf32.f32 %0, %1;" : "=r"(u) : "f"(f)); return u;
}
__device__ __forceinline__ void mma8(float c[4], const unsigned a[4], const unsigned b[2]) {
    asm volatile("mma.sync.aligned.m16n8k8.row.col.f32.tf32.tf32.f32 "
        "{%0,%1,%2,%3},{%4,%5,%6,%7},{%8,%9},{%0,%1,%2,%3};"
        : "+f"(c[0]), "+f"(c[1]), "+f"(c[2]), "+f"(c[3])
        : "r"(a[0]), "r"(a[1]), "r"(a[2]), "r"(a[3]), "r"(b[0]), "r"(b[1]));
}

// ---------------- scratch (device globals; no allocations allowed) --------
__device__ float g_x[BT * Ec];
__device__ float g_h[BT * Ec];
__device__ float g_qkv[BT * 3 * Ec];
__device__ float g_y[BT * Ec];
__device__ float g_fc[BT * 2 * Ec];
__device__ float g_part[64 * Ec];

// ---------------- embed ----------------
__global__ void embed_kernel(const float* __restrict__ X,
                             const float* __restrict__ wpe,
                             float* __restrict__ out) {
    int i4 = blockIdx.x * 256 + threadIdx.x;
    int e4 = i4 & (Ec / 4 - 1);
    int t  = (i4 >> 6) & (Tc - 1);
    float4 x  = ((const float4*)X)[i4];
    float4 w  = ((const float4*)wpe)[t * (Ec / 4) + e4];
    float4 w2 = ((const float4*)wpe)[(t >= Tc / 2 ? 1 : 0) * (Ec / 4) + e4];
    float4 o;
    o.x = fmaxf(x.x + w.x + w2.x, 0.f);
    o.y = fmaxf(x.y + w.y + w2.y, 0.f);
    o.z = fmaxf(x.z + w.z + w2.z, 0.f);
    o.w = fmaxf(x.w + w.w + w2.w, 0.f);
    ((float4*)out)[i4] = o;
}

// ---------------- layernorm ----------------
__global__ void ln_kernel(const float* __restrict__ in,
                          const float* __restrict__ g,
                          const float* __restrict__ b,
                          float* __restrict__ out, int relu_out) {
    int row = blockIdx.x;
    int tid = threadIdx.x;
    __shared__ float rb[8];
    float v = in[row * Ec + tid];
    float s = v;
    #pragma unroll
    for (int o = 16; o; o >>= 1) s += __shfl_xor_sync(~0u, s, o);
    if ((tid & 31) == 0) rb[tid >> 5] = s;
    __syncthreads();
    float tot = 0;
    #pragma unroll
    for (int i = 0; i < 8; i++) tot += rb[i];
    float mu = tot * (1.f / Ec);
    float d = v - mu;
    float s2 = d * d;
    #pragma unroll
    for (int o = 16; o; o >>= 1) s2 += __shfl_xor_sync(~0u, s2, o);
    __syncthreads();
    if ((tid & 31) == 0) rb[tid >> 5] = s2;
    __syncthreads();
    float tot2 = 0;
    #pragma unroll
    for (int i = 0; i < 8; i++) tot2 += rb[i];
    float r = rsqrtf(tot2 * (1.f / Ec) + 1e-5f);
    float o = d * r * g[tid] + b[tid];
    if (relu_out) o = fmaxf(o, 0.f);
    out[row * Ec + tid] = o;
}

// ---------------- GEMM (tf32 tensor cores): C = act(A @ W^T + bias (+res))
// 128x128 tile, BK=64 chunks, 8 warps (4 q-strips x 2 n-strips), m16n8k8.
constexpr int GEMM_SMEM = 2 * 128 * GP * 4;   // 69632 B

__global__ void __launch_bounds__(256)
gemm_tc_kernel(const float* __restrict__ A, const float* __restrict__ W,
               const float* __restrict__ bias, const float* __restrict__ res,
               float* __restrict__ C, int M, int N, int K, int relu, int addres) {
    extern __shared__ unsigned gsm[];
    unsigned* As = gsm;                 // [128][GP]
    unsigned* Ws = gsm + 128 * GP;      // [128][GP]

    int tid = threadIdx.x;
    int lane = tid & 31, wid = tid >> 5;
    int g = lane >> 2, tig = lane & 3;
    int wm = wid >> 1, wn = wid & 1;
    int bm = blockIdx.y * 128, bn = blockIdx.x * 128;

    float acc[2][8][4];
    #pragma unroll
    for (int ma = 0; ma < 2; ma++)
        #pragma unroll
        for (int na = 0; na < 8; na++)
            #pragma unroll
            for (int r = 0; r < 4; r++) acc[ma][na][r] = 0.f;

    for (int k0 = 0; k0 < K; k0 += 64) {
        __syncthreads();
        // load A[128][64] and W[128][64] chunks -> tf32 smem
        #pragma unroll
        for (int i = 0; i < 8; i++) {
            int idx = i * 256 + tid;
            int c4 = idx & 15, r = idx >> 4;
            float4 va = *(const float4*)(A + (long)(bm + r) * K + k0 + c4 * 4);
            *(uint4*)(As + r * GP + c4 * 4) =
                make_uint4(f2tf(va.x), f2tf(va.y), f2tf(va.z), f2tf(va.w));
            float4 vw = *(const float4*)(W + (long)(bn + r) * K + k0 + c4 * 4);
            *(uint4*)(Ws + r * GP + c4 * 4) =
                make_uint4(f2tf(vw.x), f2tf(vw.y), f2tf(vw.z), f2tf(vw.w));
        }
        __syncthreads();

        #pragma unroll
        for (int ks = 0; ks < 8; ks++) {
            int d0 = ks * 8;
            unsigned a[2][4];
            #pragma unroll
            for (int ma = 0; ma < 2; ma++) {
                int mr = wm * 32 + ma * 16;
                a[ma][0] = As[(mr + g) * GP + d0 + tig];
                a[ma][1] = As[(mr + g + 8) * GP + d0 + tig];
                a[ma][2] = As[(mr + g) * GP + d0 + tig + 4];
                a[ma][3] = As[(mr + g + 8) * GP + d0 + tig + 4];
            }
            #pragma unroll
            for (int na = 0; na < 8; na++) {
                int nc = wn * 64 + na * 8 + g;
                unsigned b[2] = { Ws[nc * GP + d0 + tig], Ws[nc * GP + d0 + tig + 4] };
                mma8(acc[0][na], a[0], b);
                mma8(acc[1][na], a[1], b);
            }
        }
    }

    // epilogue: bias (+res) (+relu)
    #pragma unroll
    for (int ma = 0; ma < 2; ma++)
        #pragma unroll
        for (int na = 0; na < 8; na++) {
            int row0 = bm + wm * 32 + ma * 16 + g;
            int col  = bn + wn * 64 + na * 8 + 2 * tig;
            float* c = acc[ma][na];
            float b0 = bias[col], b1 = bias[col + 1];
            float v0 = c[0] + b0, v1 = c[1] + b1;
            float v2 = c[2] + b0, v3 = c[3] + b1;
            if (addres) {
                float2 r0 = *(const float2*)(res + (long)row0 * N + col);
                float2 r1 = *(const float2*)(res + (long)(row0 + 8) * N + col);
                v0 += r0.x; v1 += r0.y; v2 += r1.x; v3 += r1.y;
            }
            if (relu) {
                v0 = fmaxf(v0, 0.f); v1 = fmaxf(v1, 0.f);
                v2 = fmaxf(v2, 0.f); v3 = fmaxf(v3, 0.f);
            }
            *(float2*)(C + (long)row0 * N + col)       = make_float2(v0, v1);
            *(float2*)(C + (long)(row0 + 8) * N + col) = make_float2(v2, v3);
        }
}

// ---------------- attention: tf32 mma.sync (m16n8k8) ----------------------
constexpr int ATTN_SMEM = 3 * 128 * P * 4;   // 202752 B

__device__ __forceinline__ void load_tile_tf32(const float* __restrict__ src,
                                               unsigned* dst, int tid) {
    #pragma unroll
    for (int i = 0; i < 16; i++) {
        int idx = i * 256 + tid;
        int d4 = idx & 31, r = idx >> 5;
        float4 v = *(const float4*)(src + (long)r * 768 + d4 * 4);
        uint4 u = make_uint4(f2tf(v.x), f2tf(v.y), f2tf(v.z), f2tf(v.w));
        *(uint4*)(dst + r * P + d4 * 4) = u;
    }
}

__device__ __forceinline__ void attn_tile(const float* __restrict__ qkv,
                                          float* __restrict__ y,
                                          unsigned* Qs, unsigned* Ks, unsigned* Vs,
                                          int qt, int baserow, int h, int tid) {
    const float scale = 0.08838834764831845f;   // 1/sqrt(128)
    int lane = tid & 31, wid = tid >> 5;
    int g = lane >> 2, tig = lane & 3;
    int wm = wid >> 1, wn = wid & 1;
    unsigned* Ss = Ks;   // alias: S over K's region (dead after S phase)

    load_tile_tf32(qkv + (long)(baserow + qt * QT2) * 768 + h * HDc, Qs, tid);

    float yacc[2][8][4];
    #pragma unroll
    for (int ma = 0; ma < 2; ma++)
        #pragma unroll
        for (int na = 0; na < 8; na++)
            #pragma unroll
            for (int r = 0; r < 4; r++) yacc[ma][na][r] = 0.f;

    for (int kt = 0; kt <= qt; kt++) {
        __syncthreads();
        const float* kvb = qkv + (long)(baserow + kt * KT2) * 768 + h * HDc;
        load_tile_tf32(kvb + 256, Ks, tid);
        load_tile_tf32(kvb + 512, Vs, tid);
        __syncthreads();

        // ---- S = Q @ K^T ----
        float sacc[2][8][4];
        #pragma unroll
        for (int ma = 0; ma < 2; ma++)
            #pragma unroll
            for (int na = 0; na < 8; na++)
                #pragma unroll
                for (int r = 0; r < 4; r++) sacc[ma][na][r] = 0.f;

        #pragma unroll 4
        for (int ks = 0; ks < 16; ks++) {
            int d0 = ks * 8;
            unsigned a[2][4];
            #pragma unroll
            for (int ma = 0; ma < 2; ma++) {
                int qr = wm * 32 + ma * 16;
                a[ma][0] = Qs[(qr + g) * P + d0 + tig];
                a[ma][1] = Qs[(qr + g + 8) * P + d0 + tig];
                a[ma][2] = Qs[(qr + g) * P + d0 + tig + 4];
                a[ma][3] = Qs[(qr + g + 8) * P + d0 + tig + 4];
            }
            #pragma unroll
            for (int na = 0; na < 8; na++) {
                int kc = wn * 64 + na * 8 + g;
                unsigned b[2] = { Ks[kc * P + d0 + tig], Ks[kc * P + d0 + tig + 4] };
                mma8(sacc[0][na], a[0], b);
                mma8(sacc[1][na], a[1], b);
            }
        }
        __syncthreads();   // all Ks reads done; Ss may overwrite

        #pragma unroll
        for (int ma = 0; ma < 2; ma++)
            #pragma unroll
            for (int na = 0; na < 8; na++) {
                int lq0 = wm * 32 + ma * 16 + g;
                int lk  = wn * 64 + na * 8 + 2 * tig;
                int qg0 = qt * QT2 + lq0, qg1 = qg0 + 8;
                int kg  = kt * KT2 + lk;
                float* c = sacc[ma][na];
                float v0 = (kg     <= qg0) ? fmaxf(c[0] * scale, 0.f) : 0.f;
                float v1 = (kg + 1 <= qg0) ? fmaxf(c[1] * scale, 0.f) : 0.f;
                float v2 = (kg     <= qg1) ? fmaxf(c[2] * scale, 0.f) : 0.f;
                float v3 = (kg + 1 <= qg1) ? fmaxf(c[3] * scale, 0.f) : 0.f;
                *(uint2*)(Ss + lq0 * P + lk)       = make_uint2(f2tf(v0), f2tf(v1));
                *(uint2*)(Ss + (lq0 + 8) * P + lk) = make_uint2(f2tf(v2), f2tf(v3));
            }
        __syncthreads();   // Ss visible

        // ---- Y += S @ V ----
        #pragma unroll 4
        for (int ks = 0; ks < 16; ks++) {
            int kp0 = ks * 8;
            unsigned a[2][4];
            #pragma unroll
            for (int ma = 0; ma < 2; ma++) {
                int qr = wm * 32 + ma * 16;
                a[ma][0] = Ss[(qr + g) * P + kp0 + tig];
                a[ma][1] = Ss[(qr + g + 8) * P + kp0 + tig];
                a[ma][2] = Ss[(qr + g) * P + kp0 + tig + 4];
                a[ma][3] = Ss[(qr + g + 8) * P + kp0 + tig + 4];
            }
            #pragma unroll
            for (int na = 0; na < 8; na++) {
                int dc = wn * 64 + na * 8 + g;
                unsigned b[2] = { Vs[(kp0 + tig) * P + dc], Vs[(kp0 + tig + 4) * P + dc] };
                mma8(yacc[0][na], a[0], b);
                mma8(yacc[1][na], a[1], b);
            }
        }
    }

    #pragma unroll
    for (int ma = 0; ma < 2; ma++)
        #pragma unroll
        for (int na = 0; na < 8; na++) {
            int row0 = baserow + qt * QT2 + wm * 32 + ma * 16 + g;
            int col  = h * HDc + wn * 64 + na * 8 + 2 * tig;
            float* c = yacc[ma][na];
            *(float2*)(y + (long)row0 * Ec + col)       = make_float2(c[0], c[1]);
            *(float2*)(y + (long)(row0 + 8) * Ec + col) = make_float2(c[2], c[3]);
        }
}

__global__ void __launch_bounds__(256, 1)
attn_kernel(const float* __restrict__ qkv, float* __restrict__ y) {
    extern __shared__ unsigned smu[];
    unsigned* Qs = smu;
    unsigned* Ks = smu + 128 * P;
    unsigned* Vs = smu + 2 * 128 * P;

    int pair = blockIdx.x;
    int bh = blockIdx.y;
    int b = bh >> 1, h = bh & 1;
    int baserow = b * Tc;

    attn_tile(qkv, y, Qs, Ks, Vs, NQT2 - 1 - pair, baserow, h, threadIdx.x);
    __syncthreads();
    attn_tile(qkv, y, Qs, Ks, Vs, pair, baserow, h, threadIdx.x);
}

// ---------------- mean over T ----------------
__global__ void meanpart_kernel(const float* __restrict__ xf, float* __restrict__ part) {
    int c = blockIdx.x;
    int b = blockIdx.y;
    int e = threadIdx.x;
    float s = 0.f;
    for (int tt = 0; tt < 256; tt++) {
        int t = c * 256 + tt;
        s += xf[(b * Tc + t) * Ec + e];
    }
    part[(c * Bc + b) * Ec + e] = s;
}

// ---------------- final ----------------
__global__ void final_kernel(const float* __restrict__ part,
                             const float* __restrict__ head_w,
                             const float* __restrict__ head_b,
                             const float* __restrict__ Y,
                             float* __restrict__ out) {
    __shared__ float emb[Bc * Ec];
    __shared__ float lg[Bc * M2c];
    __shared__ float rb[8];
    int tid = threadIdx.x;

    for (int i = tid; i < Bc * Ec; i += 256) {
        int b = i >> 8, e = i & 255;
        float s = 0.f;
        #pragma unroll
        for (int c = 0; c < 8; c++) s += part[(c * Bc + b) * Ec + e];
        emb[i] = s * (1.f / Tc);
    }
    __syncthreads();

    float l1 = 0.f;
    for (int o = tid; o < Bc * M2c; o += 256) {
        int b = o / M2c, m = o % M2c;
        float s = head_b[m];
        const float* wr = head_w + m * Ec;
        const float* er = emb + b * Ec;
        #pragma unroll 4
        for (int k = 0; k < Ec; k++) s += er[k] * wr[k];
        s = fmaxf(s, 0.f);
        lg[o] = s;
        float d = s - Y[o];
        l1 += d * d;
    }
    #pragma unroll
    for (int o = 16; o; o >>= 1) l1 += __shfl_xor_sync(~0u, l1, o);
    __syncthreads();
    if ((tid & 31) == 0) rb[tid >> 5] = l1;
    __syncthreads();
    float tot1 = 0.f;
    #pragma unroll
    for (int i = 0; i < 8; i++) tot1 += rb[i];
    float loss1 = sqrtf(tot1 / (float)(Bc * M2c));

    float l3 = 0.f;
    for (int i = tid; i < Bc * (Ec / 2); i += 256) {
        int b = i / (Ec / 2), j = i % (Ec / 2);
        float e1 = emb[b * Ec + j];
        float e2 = emb[b * Ec + Ec / 2 + j];
        out[i] = e1;
        out[Bc * (Ec / 2) + i] = e2;
        float d = e1 - e2;
        l3 += d * d;
    }
    #pragma unroll
    for (int o = 16; o; o >>= 1) l3 += __shfl_xor_sync(~0u, l3, o);
    __syncthreads();
    if ((tid & 31) == 0) rb[tid >> 5] = l3;
    __syncthreads();
    float tot3 = 0.f;
    #pragma unroll
    for (int i = 0; i < 8; i++) tot3 += rb[i];
    float loss3 = sqrtf(tot3 / (float)(Bc * Ec / 2));

    int off = 2 * Bc * (Ec / 2);
    if (tid == 0) {
        out[off + 0] = 50.f * loss1 + loss3;
        out[off + 1] = loss1;
        out[off + 2] = loss3;
    }
    for (int o = tid; o < Bc * M2c; o += 256) out[off + 3 + o] = lg[o];
}

// ---------------- host launcher ----------------
extern "C" void kernel_launch(void* const* d_in, const int* in_sizes, int n_in,
                              void* d_out, int out_size) {
    const float* X          = (const float*)d_in[0];
    const float* Y          = (const float*)d_in[1];
    const float* wpe        = (const float*)d_in[2];
    const float* ln1_g      = (const float*)d_in[3];
    const float* ln1_b      = (const float*)d_in[4];
    const float* attn_w     = (const float*)d_in[5];
    const float* attn_b     = (const float*)d_in[6];
    const float* attnproj_w = (const float*)d_in[7];
    const float* attnproj_b = (const float*)d_in[8];
    const float* ln2_g      = (const float*)d_in[9];
    const float* ln2_b      = (const float*)d_in[10];
    const float* fc_w       = (const float*)d_in[11];
    const float* fc_b       = (const float*)d_in[12];
    const float* mlpproj_w  = (const float*)d_in[13];
    const float* mlpproj_b  = (const float*)d_in[14];
    const float* lnf_g      = (const float*)d_in[15];
    const float* lnf_b      = (const float*)d_in[16];
    const float* head_w     = (const float*)d_in[17];
    const float* head_b     = (const float*)d_in[18];

    float *x, *h, *qkv, *y, *fc, *part;
    cudaGetSymbolAddress((void**)&x, g_x);
    cudaGetSymbolAddress((void**)&h, g_h);
    cudaGetSymbolAddress((void**)&qkv, g_qkv);
    cudaGetSymbolAddress((void**)&y, g_y);
    cudaGetSymbolAddress((void**)&fc, g_fc);
    cudaGetSymbolAddress((void**)&part, g_part);

    cudaFuncSetAttribute(attn_kernel, cudaFuncAttributeMaxDynamicSharedMemorySize, ATTN_SMEM);
    cudaFuncSetAttribute(attn_kernel, cudaFuncAttributePreferredSharedMemoryCarveout,
                         cudaSharedmemCarveoutMaxShared);
    cudaFuncSetAttribute(gemm_tc_kernel, cudaFuncAttributeMaxDynamicSharedMemorySize, GEMM_SMEM);

    embed_kernel<<<BT * Ec / 4 / 256, 256>>>(X, wpe, x);
    ln_kernel<<<BT, 256>>>(x, ln1_g, ln1_b, h, 0);
    gemm_tc_kernel<<<dim3(768 / 128, BT / 128), 256, GEMM_SMEM>>>(h, attn_w, attn_b, nullptr, qkv, BT, 768, 256, 1, 0);
    attn_kernel<<<dim3(NQT2 / 2, Bc * Hc), 256, ATTN_SMEM>>>(qkv, y);
    gemm_tc_kernel<<<dim3(256 / 128, BT / 128), 256, GEMM_SMEM>>>(y, attnproj_w, attnproj_b, x, x, BT, 256, 256, 0, 1);
    ln_kernel<<<BT, 256>>>(x, ln2_g, ln2_b, h, 0);
    gemm_tc_kernel<<<dim3(512 / 128, BT / 128), 256, GEMM_SMEM>>>(h, fc_w, fc_b, nullptr, fc, BT, 512, 256, 1, 0);
    gemm_tc_kernel<<<dim3(256 / 128, BT / 128), 256, GEMM_SMEM>>>(fc, mlpproj_w, mlpproj_b, x, x, BT, 256, 512, 1, 1);
    ln_kernel<<<BT, 256>>>(x, lnf_g, lnf_b, h, 1);
    meanpart_kernel<<<dim3(8, Bc), 256>>>(h, part);
    final_kernel<<<1, 256>>>(part, head_w, head_b, Y, (float*)d_out);
}